// round 11
// baseline (speedup 1.0000x reference)
#include <cuda_runtime.h>
#include <cuda_bf16.h>
#include <math.h>

#define BATCH 128
#define TSEQ  64
#define VOCAB 10000
#define EMB   1024
#define HID   1024
#define NBLK  148
#define BH    (BATCH*HID)
#define NPAD  10240
#define XP3   3072

typedef unsigned long long ull;
typedef __nv_bfloat16 bf16;

__device__ __forceinline__ float sigf(float x) { return 1.f / (1.f + expf(-x)); }

// ---------------- mma.sync helpers ----------------
__device__ __forceinline__ unsigned smem_u32(const void* p) {
    unsigned a;
    asm("{ .reg .u64 t; cvta.to.shared.u64 t, %1; cvt.u32.u64 %0, t; }" : "=r"(a) : "l"(p));
    return a;
}
__device__ __forceinline__ void ldsm4(unsigned* r, unsigned a) {
    asm volatile("ldmatrix.sync.aligned.m8n8.x4.shared.b16 {%0,%1,%2,%3}, [%4];"
                 : "=r"(r[0]), "=r"(r[1]), "=r"(r[2]), "=r"(r[3]) : "r"(a));
}
__device__ __forceinline__ void mma16816(float* c, const unsigned* a, unsigned b0, unsigned b1) {
    asm volatile("mma.sync.aligned.m16n8k16.row.col.f32.bf16.bf16.f32 "
                 "{%0,%1,%2,%3}, {%4,%5,%6,%7}, {%8,%9}, {%0,%1,%2,%3};"
                 : "+f"(c[0]), "+f"(c[1]), "+f"(c[2]), "+f"(c[3])
                 : "r"(a[0]), "r"(a[1]), "r"(a[2]), "r"(a[3]), "r"(b0), "r"(b1));
}
__device__ __forceinline__ void cpa16(unsigned saddr, const void* g) {
    asm volatile("cp.async.ca.shared.global [%0], [%1], 16;" :: "r"(saddr), "l"(g));
}
__device__ __forceinline__ void cpg16(unsigned saddr, const void* g) {
    asm volatile("cp.async.cg.shared.global [%0], [%1], 16;" :: "r"(saddr), "l"(g));
}
#define GBAR(id) asm volatile("bar.sync %0, 256;" :: "r"(id) : "memory")

// ---------------- device scratch ----------------
__device__ float g_xp[TSEQ*BATCH*XP3];
__device__ float g_h0buf[2*BH];
__device__ float g_h1buf[2*BH];
__device__ float g_pA[8*128*2048];
__device__ float g_pB[16*128*1024];
__device__ float g_pC[8*128*2048];
__device__ float g_pD[16*128*1024];
__device__ float g_bias3[XP3];
__device__ bf16 g_ah[TSEQ*BH];
__device__ bf16 g_al[TSEQ*BH];
__device__ bf16 g_bth[NPAD*1024];
__device__ bf16 g_btl[NPAD*1024];
__device__ bf16 g_wt0h[3*1024*1024];
__device__ bf16 g_wt0l[3*1024*1024];
__device__ bf16 g_wt1h[3*1024*2048];
__device__ bf16 g_wt1l[3*1024*2048];
__device__ bf16 g_h0h[2*BH], g_h0l[2*BH];
__device__ bf16 g_h1h[2*BH], g_h1l[2*BH];
__device__ bf16 g_rh0h[BH], g_rh0l[BH];
__device__ bf16 g_rh1h[BH], g_rh1l[BH];
__device__ unsigned g_barcnt;
__device__ volatile unsigned g_barsense;

__device__ __forceinline__ void bsplit2(bf16* bh, bf16* bl, size_t idx, float2 v) {
    bf16 h0 = __float2bfloat16(v.x), h1 = __float2bfloat16(v.y);
    bf16 l0 = __float2bfloat16(v.x - __bfloat162float(h0));
    bf16 l1 = __float2bfloat16(v.y - __bfloat162float(h1));
    *(__nv_bfloat162*)(bh + idx) = __halves2bfloat162(h0, h1);
    *(__nv_bfloat162*)(bl + idx) = __halves2bfloat162(l0, l1);
}

// ---------------- small kernels ----------------
__global__ void gather_kernel(const int* __restrict__ tok, const float* __restrict__ emb) {
    int row = blockIdx.x;
    int t = row >> 7, b = row & 127;
    int token = tok[b * TSEQ + t];
    float4 v = ((const float4*)(emb + (size_t)token * EMB))[threadIdx.x];
    size_t idx = (size_t)row * EMB + threadIdx.x * 4;
    bsplit2(g_ah, g_al, idx,     make_float2(v.x, v.y));
    bsplit2(g_ah, g_al, idx + 2, make_float2(v.z, v.w));
}

__global__ void init_h(const float* __restrict__ ihs) {
    int i = (blockIdx.x * blockDim.x + threadIdx.x) * 2;
    if (i < BH) {
        float2 a = *(const float2*)&ihs[i];
        float2 b = *(const float2*)&ihs[BH + i];
        *(float2*)&g_h0buf[i] = a;
        *(float2*)&g_h1buf[i] = b;
        bsplit2(g_h0h, g_h0l, i, a);
        bsplit2(g_h1h, g_h1l, i, b);
    }
}

__global__ void concat_bias(const float* __restrict__ bu, const float* __restrict__ br,
                            const float* __restrict__ bc) {
    int i = blockIdx.x * blockDim.x + threadIdx.x;
    if (i < 1024) {
        g_bias3[i]        = bu[i];
        g_bias3[1024 + i] = br[i];
        g_bias3[2048 + i] = bc[i];
    }
}

__global__ void state_out(float* __restrict__ out, long long out_size) {
    long long i = (long long)blockIdx.x * blockDim.x + threadIdx.x;
    long long base = (long long)BATCH * TSEQ * VOCAB;
    if (i < BH) {
        if (base + i < out_size)      out[base + i]      = g_h0buf[i];
        if (base + BH + i < out_size) out[base + BH + i] = g_h1buf[i];
    }
}

__global__ void tconv(const float* __restrict__ W, int ldw, int N, int ldo,
                      bf16* __restrict__ th, bf16* __restrict__ tl) {
    __shared__ float t[32][33];
    int n0 = blockIdx.x * 32, k0 = blockIdx.y * 32;
    int tx = threadIdx.x, ty = threadIdx.y;
    #pragma unroll
    for (int r = 0; r < 4; ++r) {
        int k = k0 + ty + r * 8, n = n0 + tx;
        t[ty + r * 8][tx] = (n < N) ? W[(size_t)k * ldw + n] : 0.f;
    }
    __syncthreads();
    #pragma unroll
    for (int r = 0; r < 4; ++r) {
        int n = n0 + ty + r * 8, k = k0 + tx;
        float x = t[tx][ty + r * 8];
        bf16 hh = __float2bfloat16(x);
        th[(size_t)n * ldo + k] = hh;
        tl[(size_t)n * ldo + k] = __float2bfloat16(x - __bfloat162float(hh));
    }
}

// ---------------- mma.sync bf16-split GEMM (pre + logits) — unchanged, at HMMA ceiling ----------------
#define MM_LD 40
#define MM_MS (128*MM_LD)
#define MM_STG (4*MM_MS)

template<int MODE>
__global__ __launch_bounds__(256, 2)
void mma_gemm(const bf16* __restrict__ Ah, const bf16* __restrict__ Al,
              const bf16* __restrict__ Bh, const bf16* __restrict__ Bl,
              const float* __restrict__ bias, float* __restrict__ C, int N)
{
    extern __shared__ __align__(16) bf16 sm[];
    const int tid = threadIdx.x, w = tid >> 5, l = tid & 31;
    const int m0 = blockIdx.x * 128, n0 = blockIdx.y * 128;
    const int mw = (w >> 2) * 64, nw = (w & 3) * 32;
    const unsigned sbase = smem_u32(sm);

    float acc[4][4][4];
    #pragma unroll
    for (int i = 0; i < 4; ++i)
        #pragma unroll
        for (int j = 0; j < 4; ++j)
            #pragma unroll
            for (int q = 0; q < 4; ++q) acc[i][j][q] = 0.f;

    auto stage_load = [&](int c, int s) {
        int kc = c * 32;
        unsigned sb = sbase + (unsigned)(s * MM_STG) * 2;
        #pragma unroll
        for (int l2 = 0; l2 < 2; ++l2) {
            int u = tid + l2 * 256;
            int row = u >> 2, q = u & 3;
            unsigned soff = (unsigned)(row * MM_LD + q * 8) * 2;
            size_t ga = (size_t)(m0 + row) * 1024 + kc + q * 8;
            size_t gb = (size_t)(n0 + row) * 1024 + kc + q * 8;
            cpa16(sb + 0 * MM_MS * 2 + soff, Ah + ga);
            cpa16(sb + 1 * MM_MS * 2 + soff, Al + ga);
            cpa16(sb + 2 * MM_MS * 2 + soff, Bh + gb);
            cpa16(sb + 3 * MM_MS * 2 + soff, Bl + gb);
        }
    };

    stage_load(0, 0);
    asm volatile("cp.async.commit_group;" ::: "memory");
    const int ldrow = ((l >> 3) & 1) * 8 + (l & 7);
    const int ldcol = (l >> 4) * 8;

    for (int c = 0; c < 32; ++c) {
        if (c + 1 < 32) {
            stage_load(c + 1, (c + 1) & 1);
            asm volatile("cp.async.commit_group;" ::: "memory");
            asm volatile("cp.async.wait_group 1;" ::: "memory");
        } else {
            asm volatile("cp.async.wait_group 0;" ::: "memory");
        }
        __syncthreads();
        unsigned sb = sbase + (unsigned)((c & 1) * MM_STG) * 2;
        #pragma unroll
        for (int kk = 0; kk < 2; ++kk) {
            unsigned aH[4][4], aL[4][4], bH[4][2], bL[4][2];
            #pragma unroll
            for (int mt = 0; mt < 4; ++mt) {
                int r = mw + mt * 16 + ldrow;
                unsigned ad = sb + (unsigned)(r * MM_LD + kk * 16 + ldcol) * 2;
                ldsm4(aH[mt], ad);
                ldsm4(aL[mt], ad + MM_MS * 2);
            }
            #pragma unroll
            for (int p = 0; p < 2; ++p) {
                int r = nw + p * 16 + ldrow;
                unsigned bd = sb + (unsigned)(2 * MM_MS + r * MM_LD + kk * 16 + ldcol) * 2;
                unsigned t0[4], t1[4];
                ldsm4(t0, bd);
                ldsm4(t1, bd + MM_MS * 2);
                bH[2*p][0] = t0[0]; bH[2*p][1] = t0[2];
                bH[2*p+1][0] = t0[1]; bH[2*p+1][1] = t0[3];
                bL[2*p][0] = t1[0]; bL[2*p][1] = t1[2];
                bL[2*p+1][0] = t1[1]; bL[2*p+1][1] = t1[3];
            }
            #pragma unroll
            for (int mt = 0; mt < 4; ++mt)
                #pragma unroll
                for (int nt = 0; nt < 4; ++nt) {
                    mma16816(acc[mt][nt], aH[mt], bH[nt][0], bH[nt][1]);
                    mma16816(acc[mt][nt], aH[mt], bL[nt][0], bL[nt][1]);
                    mma16816(acc[mt][nt], aL[mt], bH[nt][0], bH[nt][1]);
                }
        }
        __syncthreads();
    }

    int g = l >> 2, tg = l & 3;
    #pragma unroll
    for (int mt = 0; mt < 4; ++mt) {
        int r0 = m0 + mw + mt * 16 + g;
        int r1 = r0 + 8;
        float *crow0, *crow1;
        if (MODE == 0) {
            crow0 = C + (size_t)r0 * N;
            crow1 = C + (size_t)r1 * N;
        } else {
            crow0 = C + ((size_t)(r0 & 127) * TSEQ + (r0 >> 7)) * N;
            crow1 = C + ((size_t)(r1 & 127) * TSEQ + (r1 >> 7)) * N;
        }
        #pragma unroll
        for (int nt = 0; nt < 4; ++nt) {
            int n = n0 + nw + nt * 8 + tg * 2;
            if (MODE == 0 || n < N) {
                float2 bv = *(const float2*)&bias[n];
                *(float2*)&crow0[n] = make_float2(acc[mt][nt][0] + bv.x, acc[mt][nt][1] + bv.y);
                *(float2*)&crow1[n] = make_float2(acc[mt][nt][2] + bv.x, acc[mt][nt][3] + bv.y);
            }
        }
    }
}

// ---------------- recurrence MMA: per-GROUP job, 256 thr/group, tile 128x64 ----------------
// Two groups per 512-thread CTA act as two co-resident CTAs (named barriers).
#define GR_A  (128*MM_LD)            // 5120 elems per A matrix
#define GR_B  (64*MM_LD)             // 2560 elems per B matrix
#define GR_STAGE (2*GR_A + 2*GR_B)   // 15360 elems
#define GR_GRP (2*GR_STAGE)          // per-group 2 stages = 30720 elems

__device__ __noinline__ void rec_mma_g(
    int grp, int tid2,
    const bf16* Ah, const bf16* Al, int akoff,
    const bf16* Bh, const bf16* Bl, int bkoff, int ldb,
    int n0, int kchunks, float* outp, int outW, bf16* smg)
{
    const int w = tid2 >> 5, l = tid2 & 31;
    const int mw = (w >> 2) * 64, nw = (w & 3) * 16;
    const unsigned sbase = smem_u32(smg);
    const int barid = grp + 1;

    float acc[4][2][4];
    #pragma unroll
    for (int i = 0; i < 4; ++i)
        #pragma unroll
        for (int j = 0; j < 2; ++j)
            #pragma unroll
            for (int q = 0; q < 4; ++q) acc[i][j][q] = 0.f;

    auto stage_load = [&](int c, int s) {
        int kc = c * 32;
        unsigned sb = sbase + (unsigned)(s * GR_STAGE) * 2;
        #pragma unroll
        for (int l2 = 0; l2 < 2; ++l2) {          // A: 512 units per matrix
            int u = tid2 + l2 * 256;
            int row = u >> 2, q = u & 3;
            unsigned soff = (unsigned)(row * MM_LD + q * 8) * 2;
            size_t ga = (size_t)row * 1024 + akoff + kc + q * 8;
            cpg16(sb + soff,              Ah + ga);
            cpg16(sb + GR_A * 2 + soff,   Al + ga);
        }
        {                                          // B: 256 units per matrix
            int row = tid2 >> 2, q = tid2 & 3;
            unsigned soff = (unsigned)(row * MM_LD + q * 8) * 2;
            size_t gb = (size_t)(n0 + row) * ldb + bkoff + kc + q * 8;
            cpg16(sb + 2 * GR_A * 2 + soff,           Bh + gb);
            cpg16(sb + (2 * GR_A + GR_B) * 2 + soff,  Bl + gb);
        }
    };

    stage_load(0, 0);
    asm volatile("cp.async.commit_group;" ::: "memory");
    const int ldrow = ((l >> 3) & 1) * 8 + (l & 7);
    const int ldcol = (l >> 4) * 8;

    for (int c = 0; c < kchunks; ++c) {
        if (c + 1 < kchunks) {
            stage_load(c + 1, (c + 1) & 1);
            asm volatile("cp.async.commit_group;" ::: "memory");
            asm volatile("cp.async.wait_group 1;" ::: "memory");
        } else {
            asm volatile("cp.async.wait_group 0;" ::: "memory");
        }
        GBAR(barid);
        unsigned sb = sbase + (unsigned)((c & 1) * GR_STAGE) * 2;
        #pragma unroll
        for (int kk = 0; kk < 2; ++kk) {
            unsigned aH[4][4], aL[4][4], bH[2][2], bL[2][2];
            #pragma unroll
            for (int mt = 0; mt < 4; ++mt) {
                int r = mw + mt * 16 + ldrow;
                unsigned ad = sb + (unsigned)(r * MM_LD + kk * 16 + ldcol) * 2;
                ldsm4(aH[mt], ad);
                ldsm4(aL[mt], ad + GR_A * 2);
            }
            {
                int r = nw + ldrow;
                unsigned bd = sb + (unsigned)(2 * GR_A * MM_LD / MM_LD * MM_LD) * 0; // (placeholder removed below)
                bd = sb + (unsigned)(2 * GR_A + r * MM_LD + kk * 16 + ldcol) * 2;
                unsigned t0[4], t1[4];
                ldsm4(t0, bd);
                ldsm4(t1, bd + GR_B * 2);
                bH[0][0] = t0[0]; bH[0][1] = t0[2];
                bH[1][0] = t0[1]; bH[1][1] = t0[3];
                bL[0][0] = t1[0]; bL[0][1] = t1[2];
                bL[1][0] = t1[1]; bL[1][1] = t1[3];
            }
            #pragma unroll
            for (int mt = 0; mt < 4; ++mt)
                #pragma unroll
                for (int nt = 0; nt < 2; ++nt) {
                    mma16816(acc[mt][nt], aH[mt], bH[nt][0], bH[nt][1]);
                    mma16816(acc[mt][nt], aH[mt], bL[nt][0], bL[nt][1]);
                    mma16816(acc[mt][nt], aL[mt], bH[nt][0], bH[nt][1]);
                }
        }
        GBAR(barid);
    }

    int g = l >> 2, tg = l & 3;
    #pragma unroll
    for (int mt = 0; mt < 4; ++mt) {
        int r0 = mw + mt * 16 + g;
        int r1 = r0 + 8;
        #pragma unroll
        for (int nt = 0; nt < 2; ++nt) {
            int n = n0 + nw + nt * 8 + tg * 2;
            *(float2*)&outp[(size_t)r0 * outW + n] = make_float2(acc[mt][nt][0], acc[mt][nt][1]);
            *(float2*)&outp[(size_t)r1 * outW + n] = make_float2(acc[mt][nt][2], acc[mt][nt][3]);
        }
    }
}

// ---------------- persistent recurrence (512 thr = 2 groups) ----------------
struct RecParams {
    const float *bu1, *br1, *bc1;
};

__device__ __forceinline__ void grid_barrier(unsigned& sense) {
    __syncthreads();
    if (threadIdx.x == 0) {
        unsigned next = sense ^ 1u;
        __threadfence();
        if (atomicAdd(&g_barcnt, 1u) == NBLK - 1) {
            g_barcnt = 0;
            __threadfence();
            g_barsense = next;
        } else {
            while (g_barsense != next) __nanosleep(32);
        }
    }
    sense ^= 1u;
    __syncthreads();
}

__global__ __launch_bounds__(512, 1)
void recurrence_kernel(RecParams P)
{
    extern __shared__ __align__(16) bf16 sm[];
    unsigned sense = 0;
    const int bid = blockIdx.x;
    const int tid = threadIdx.x;
    const int grp = tid >> 8;          // 0 or 1
    const int tid2 = tid & 255;
    const int job = bid + 148 * grp;   // 0..295; jobs >= 256 idle
    bf16* smg = sm + (size_t)grp * GR_GRP;

    for (int t = 0; t < TSEQ; ++t) {
        const int cur = t & 1, nxt = cur ^ 1;
        const float* xp = g_xp + (size_t)t * BATCH * XP3;
        float* h0c = g_h0buf + (size_t)cur * BH;
        float* h0n = g_h0buf + (size_t)nxt * BH;
        float* h1c = g_h1buf + (size_t)cur * BH;
        float* h1n = g_h1buf + (size_t)nxt * BH;
        bf16 *h0ch = g_h0h + (size_t)cur * BH, *h0cl = g_h0l + (size_t)cur * BH;
        bf16 *h0nh = g_h0h + (size_t)nxt * BH, *h0nl = g_h0l + (size_t)nxt * BH;
        bf16 *h1ch = g_h1h + (size_t)cur * BH, *h1cl = g_h1l + (size_t)cur * BH;
        bf16 *h1nh = g_h1h + (size_t)nxt * BH, *h1nl = g_h1l + (size_t)nxt * BH;

        // Phase A: layer0 u,r h-part -> pA   (2g x 16n x 8k = 256 jobs, kc=4)
        if (job < 256) {
            int gg = job >> 7, nt = (job >> 3) & 15, ks = job & 7;
            rec_mma_g(grp, tid2, h0ch, h0cl, ks * 128,
                      g_wt0h + (size_t)gg * 1024 * 1024, g_wt0l + (size_t)gg * 1024 * 1024,
                      ks * 128, 1024, nt * 64, 4,
                      g_pA + (size_t)ks * 128 * 2048 + gg * 1024, 2048, smg);
        }
        grid_barrier(sense);

        // ACT A: rh0 = sig(xr + sum pA[r]) * h0c
        for (int i = bid * 512 + tid; i < BH / 2; i += NBLK * 512) {
            size_t idx = (size_t)i * 2;
            int m = (int)(idx >> 10), n = (int)(idx & 1023);
            float2 s = *(const float2*)&xp[(size_t)m * XP3 + 1024 + n];
            #pragma unroll
            for (int p = 0; p < 8; ++p) {
                float2 v = __ldcg((const float2*)&g_pA[((size_t)p * 128 + m) * 2048 + 1024 + n]);
                s.x += v.x; s.y += v.y;
            }
            float2 h = __ldcg((const float2*)&h0c[idx]);
            bsplit2(g_rh0h, g_rh0l, idx, make_float2(sigf(s.x) * h.x, sigf(s.y) * h.y));
        }
        grid_barrier(sense);

        // Phase B: layer0 candidate -> pB    (16n x 16k = 256 jobs, kc=2)
        if (job < 256) {
            int nt = job >> 4, ks = job & 15;
            rec_mma_g(grp, tid2, g_rh0h, g_rh0l, ks * 64,
                      g_wt0h + (size_t)2 * 1024 * 1024, g_wt0l + (size_t)2 * 1024 * 1024,
                      ks * 64, 1024, nt * 64, 2,
                      g_pB + (size_t)ks * 128 * 1024, 1024, smg);
        }
        grid_barrier(sense);

        // ACT B: h0n = u*h0c + (1-u)*tanh(xc + sum pB)
        for (int i = bid * 512 + tid; i < BH / 2; i += NBLK * 512) {
            size_t idx = (size_t)i * 2;
            int m = (int)(idx >> 10), n = (int)(idx & 1023);
            float2 su = *(const float2*)&xp[(size_t)m * XP3 + n];
            #pragma unroll
            for (int p = 0; p < 8; ++p) {
                float2 v = __ldcg((const float2*)&g_pA[((size_t)p * 128 + m) * 2048 + n]);
                su.x += v.x; su.y += v.y;
            }
            float2 sc = *(const float2*)&xp[(size_t)m * XP3 + 2048 + n];
            #pragma unroll
            for (int p = 0; p < 16; ++p) {
                float2 v = __ldcg((const float2*)&g_pB[((size_t)p * 128 + m) * 1024 + n]);
                sc.x += v.x; sc.y += v.y;
            }
            float2 h = __ldcg((const float2*)&h0c[idx]);
            float ux = sigf(su.x), uy = sigf(su.y);
            float2 o = make_float2(ux * h.x + (1.f - ux) * tanhf(sc.x),
                                   uy * h.y + (1.f - uy) * tanhf(sc.y));
            *(float2*)&h0n[idx] = o;
            bsplit2(h0nh, h0nl, idx, o);
        }
        grid_barrier(sense);

        // Phase C: layer1 u,r over [h0n | h1c] -> pC   (2g x 16n x 8k = 256, kc=8)
        if (job < 256) {
            int gg = job >> 7, nt = (job >> 3) & 15, ks = job & 7;
            int koff = ks * 256;
            const bf16* ah = (koff < 1024) ? h0nh : h1ch;
            const bf16* al = (koff < 1024) ? h0nl : h1cl;
            rec_mma_g(grp, tid2, ah, al, koff & 1023,
                      g_wt1h + (size_t)gg * 1024 * 2048, g_wt1l + (size_t)gg * 1024 * 2048,
                      koff, 2048, nt * 64, 8,
                      g_pC + (size_t)ks * 128 * 2048 + gg * 1024, 2048, smg);
        }
        grid_barrier(sense);

        // ACT C: rh1 = sig(br1 + sum pC[r]) * h1c
        for (int i = bid * 512 + tid; i < BH / 2; i += NBLK * 512) {
            size_t idx = (size_t)i * 2;
            int m = (int)(idx >> 10), n = (int)(idx & 1023);
            float2 s = *(const float2*)&P.br1[n];
            #pragma unroll
            for (int p = 0; p < 8; ++p) {
                float2 v = __ldcg((const float2*)&g_pC[((size_t)p * 128 + m) * 2048 + 1024 + n]);
                s.x += v.x; s.y += v.y;
            }
            float2 h = __ldcg((const float2*)&h1c[idx]);
            bsplit2(g_rh1h, g_rh1l, idx, make_float2(sigf(s.x) * h.x, sigf(s.y) * h.y));
        }
        grid_barrier(sense);

        // Phase D: layer1 candidate over [h0n | rh1] -> pD  (16n x 16k = 256, kc=4)
        if (job < 256) {
            int nt = job >> 4, ks = job & 15;
            int koff = ks * 128;
            const bf16* ah = (koff < 1024) ? h0nh : g_rh1h;
            const bf16* al = (koff < 1024) ? h0nl : g_rh1l;
            rec_mma_g(grp, tid2, ah, al, koff & 1023,
                      g_wt1h + (size_t)2 * 1024 * 2048, g_wt1l + (size_t)2 * 1024 * 2048,
                      koff, 2048, nt * 64, 4,
                      g_pD + (size_t)ks * 128 * 1024, 1024, smg);
        }
        grid_barrier(sense);

        // ACT D
        {
            bf16* seqh = g_ah + (size_t)t * BH;
            bf16* seql = g_al + (size_t)t * BH;
            for (int i = bid * 512 + tid; i < BH / 2; i += NBLK * 512) {
                size_t idx = (size_t)i * 2;
                int m = (int)(idx >> 10), n = (int)(idx & 1023);
                float2 su = *(const float2*)&P.bu1[n];
                #pragma unroll
                for (int p = 0; p < 8; ++p) {
                    float2 v = __ldcg((const float2*)&g_pC[((size_t)p * 128 + m) * 2048 + n]);
                    su.x += v.x; su.y += v.y;
                }
                float2 sc = *(const float2*)&P.bc1[n];
                #pragma unroll
                for (int p = 0; p < 16; ++p) {
                    float2 v = __ldcg((const float2*)&g_pD[((size_t)p * 128 + m) * 1024 + n]);
                    sc.x += v.x; sc.y += v.y;
                }
                float2 h = __ldcg((const float2*)&h1c[idx]);
                float ux = sigf(su.x), uy = sigf(su.y);
                float2 o = make_float2(ux * h.x + (1.f - ux) * tanhf(sc.x),
                                       uy * h.y + (1.f - uy) * tanhf(sc.y));
                *(float2*)&h1n[idx] = o;
                bsplit2(seqh, seql, idx, o);
                bsplit2(h1nh, h1nl, idx, o);
            }
        }
        grid_barrier(sense);
    }
}

// ---------------- host orchestration ----------------
extern "C" void kernel_launch(void* const* d_in, const int* in_sizes, int n_in,
                              void* d_out, int out_size)
{
    const int*   tok  = (const int*)  d_in[0];
    const float* ihs  = (const float*)d_in[1];
    const float* emb  = (const float*)d_in[2];
    const float* Wout = (const float*)d_in[3];
    const float* bout = (const float*)d_in[4];
    const float* wu0  = (const float*)d_in[5];
    const float* bu0  = (const float*)d_in[6];
    const float* wr0  = (const float*)d_in[7];
    const float* br0  = (const float*)d_in[8];
    const float* wc0  = (const float*)d_in[9];
    const float* bc0  = (const float*)d_in[10];
    const float* wu1  = (const float*)d_in[11];
    const float* bu1  = (const float*)d_in[12];
    const float* wr1  = (const float*)d_in[13];
    const float* br1  = (const float*)d_in[14];
    const float* wc1  = (const float*)d_in[15];
    const float* bc1  = (const float*)d_in[16];

    float *p_xp, *p_bias3;
    bf16 *p_ah, *p_al, *p_bth, *p_btl, *p_wt0h, *p_wt0l, *p_wt1h, *p_wt1l;
    cudaGetSymbolAddress((void**)&p_xp,    g_xp);
    cudaGetSymbolAddress((void**)&p_bias3, g_bias3);
    cudaGetSymbolAddress((void**)&p_ah,  g_ah);
    cudaGetSymbolAddress((void**)&p_al,  g_al);
    cudaGetSymbolAddress((void**)&p_bth, g_bth);
    cudaGetSymbolAddress((void**)&p_btl, g_btl);
    cudaGetSymbolAddress((void**)&p_wt0h, g_wt0h);
    cudaGetSymbolAddress((void**)&p_wt0l, g_wt0l);
    cudaGetSymbolAddress((void**)&p_wt1h, g_wt1h);
    cudaGetSymbolAddress((void**)&p_wt1l, g_wt1l);

    const int MM_SMEM  = 2 * MM_STG * 2;        // 81920 B
    const int REC_SMEM = 2 * GR_GRP * 2;        // 122880 B (2 groups x 2 stages)
    cudaFuncSetAttribute(mma_gemm<0>, cudaFuncAttributeMaxDynamicSharedMemorySize, MM_SMEM);
    cudaFuncSetAttribute(mma_gemm<1>, cudaFuncAttributeMaxDynamicSharedMemorySize, MM_SMEM);
    cudaFuncSetAttribute(recurrence_kernel, cudaFuncAttributeMaxDynamicSharedMemorySize, REC_SMEM);

    // 1) gather embeddings + bf16 split
    gather_kernel<<<TSEQ * BATCH, 256>>>(tok, emb);

    // 2) fused pre: one GEMM for all 3 layer-0 x-projections (N = 3072)
    dim3 tb(32, 8);
    tconv<<<dim3(32, 32), tb>>>(wu0, HID, HID, 1024, p_bth,               p_btl);
    tconv<<<dim3(32, 32), tb>>>(wr0, HID, HID, 1024, p_bth + 1024*1024,   p_btl + 1024*1024);
    tconv<<<dim3(32, 32), tb>>>(wc0, HID, HID, 1024, p_bth + 2*1024*1024, p_btl + 2*1024*1024);
    concat_bias<<<4, 256>>>(bu0, br0, bc0);
    mma_gemm<0><<<dim3(64, XP3 / 128), 256, MM_SMEM>>>(p_ah, p_al, p_bth, p_btl,
                                                        p_bias3, p_xp, XP3);

    // 3) recurrence weight transposes
    const size_t EH = (size_t)EMB * HID;
    tconv<<<dim3(32, 32), tb>>>(wu0 + EH, HID, HID, 1024, p_wt0h,               p_wt0l);
    tconv<<<dim3(32, 32), tb>>>(wr0 + EH, HID, HID, 1024, p_wt0h + 1024*1024,   p_wt0l + 1024*1024);
    tconv<<<dim3(32, 32), tb>>>(wc0 + EH, HID, HID, 1024, p_wt0h + 2*1024*1024, p_wt0l + 2*1024*1024);
    tconv<<<dim3(32, 64), tb>>>(wu1, HID, HID, 2048, p_wt1h,               p_wt1l);
    tconv<<<dim3(32, 64), tb>>>(wr1, HID, HID, 2048, p_wt1h + 1024*2048,   p_wt1l + 1024*2048);
    tconv<<<dim3(32, 64), tb>>>(wc1, HID, HID, 2048, p_wt1h + 2*1024*2048, p_wt1l + 2*1024*2048);

    // 4) initial hidden state
    init_h<<<(BH / 2 + 255) / 256, 256>>>(ihs);

    // 5) persistent recurrence: 512 thr = 2 co-resident MMA groups per SM
    RecParams P{bu1, br1, bc1};
    recurrence_kernel<<<NBLK, 512, REC_SMEM>>>(P);

    // 6) output projection
    tconv<<<dim3(NPAD / 32, 32), tb>>>(Wout, VOCAB, VOCAB, 1024, p_bth, p_btl);
    mma_gemm<1><<<dim3(64, NPAD / 128), 256, MM_SMEM>>>(p_ah, p_al, p_bth, p_btl,
                                                         bout, (float*)d_out, VOCAB);

    // 7) final states
    state_out<<<(BH + 255) / 256, 256>>>((float*)d_out, (long long)out_size);
}

// round 14
// speedup vs baseline: 1.0655x; 1.0655x over previous
#include <cuda_runtime.h>
#include <cuda_bf16.h>
#include <math.h>

#define BATCH 128
#define TSEQ  64
#define VOCAB 10000
#define EMB   1024
#define HID   1024
#define NBLK  148
#define RECB  128               // CTAs participating in recurrence phases
#define BH    (BATCH*HID)
#define NPAD  10240
#define NT80  (NPAD/128)        // 80 logits n-tiles
#define NJOBS (TSEQ*NT80)       // 5120 logits tiles
#define XP3   3072

typedef unsigned long long ull;
typedef __nv_bfloat16 bf16;

__device__ __forceinline__ float sigf(float x) { return 1.f / (1.f + expf(-x)); }

// ---------------- mma.sync helpers ----------------
__device__ __forceinline__ unsigned smem_u32(const void* p) {
    unsigned a;
    asm("{ .reg .u64 t; cvta.to.shared.u64 t, %1; cvt.u32.u64 %0, t; }" : "=r"(a) : "l"(p));
    return a;
}
__device__ __forceinline__ void ldsm4(unsigned* r, unsigned a) {
    asm volatile("ldmatrix.sync.aligned.m8n8.x4.shared.b16 {%0,%1,%2,%3}, [%4];"
                 : "=r"(r[0]), "=r"(r[1]), "=r"(r[2]), "=r"(r[3]) : "r"(a));
}
__device__ __forceinline__ void mma16816(float* c, const unsigned* a, unsigned b0, unsigned b1) {
    asm volatile("mma.sync.aligned.m16n8k16.row.col.f32.bf16.bf16.f32 "
                 "{%0,%1,%2,%3}, {%4,%5,%6,%7}, {%8,%9}, {%0,%1,%2,%3};"
                 : "+f"(c[0]), "+f"(c[1]), "+f"(c[2]), "+f"(c[3])
                 : "r"(a[0]), "r"(a[1]), "r"(a[2]), "r"(a[3]), "r"(b0), "r"(b1));
}
__device__ __forceinline__ void cpa16(unsigned saddr, const void* g) {
    asm volatile("cp.async.ca.shared.global [%0], [%1], 16;" :: "r"(saddr), "l"(g));
}
__device__ __forceinline__ void cpg16(unsigned saddr, const void* g) {
    asm volatile("cp.async.cg.shared.global [%0], [%1], 16;" :: "r"(saddr), "l"(g));
}

// ---------------- device scratch ----------------
__device__ float g_xp[TSEQ*BATCH*XP3];
__device__ float g_h0buf[2*BH];
__device__ float g_h1buf[2*BH];
__device__ float g_pA[8*128*2048];
__device__ float g_pB[16*128*1024];
__device__ float g_pC[8*128*2048];
__device__ float g_pD[16*128*1024];
__device__ float g_bias3[XP3];
__device__ bf16 g_ah[TSEQ*BH];           // emb splits, then h1seq splits
__device__ bf16 g_al[TSEQ*BH];
__device__ bf16 g_bth[NPAD*1024];
__device__ bf16 g_btl[NPAD*1024];
__device__ bf16 g_wt0h[3*1024*1024];
__device__ bf16 g_wt0l[3*1024*1024];
__device__ bf16 g_wt1h[3*1024*2048];
__device__ bf16 g_wt1l[3*1024*2048];
__device__ bf16 g_h0h[2*BH], g_h0l[2*BH];
__device__ bf16 g_h1h[2*BH], g_h1l[2*BH];
__device__ bf16 g_rh0h[BH], g_rh0l[BH];
__device__ bf16 g_rh1h[BH], g_rh1l[BH];
__device__ unsigned g_barcnt;
__device__ volatile unsigned g_barsense;
__device__ unsigned g_ticket;            // next logits tile to grab
__device__ volatile unsigned g_tdone;    // steps with h1 published
__device__ volatile unsigned g_recdone;  // recurrence finished flag

__device__ __forceinline__ void bsplit2(bf16* bh, bf16* bl, size_t idx, float2 v) {
    bf16 h0 = __float2bfloat16(v.x), h1 = __float2bfloat16(v.y);
    bf16 l0 = __float2bfloat16(v.x - __bfloat162float(h0));
    bf16 l1 = __float2bfloat16(v.y - __bfloat162float(h1));
    *(__nv_bfloat162*)(bh + idx) = __halves2bfloat162(h0, h1);
    *(__nv_bfloat162*)(bl + idx) = __halves2bfloat162(l0, l1);
}

// ---------------- small kernels ----------------
__global__ void gather_kernel(const int* __restrict__ tok, const float* __restrict__ emb) {
    int row = blockIdx.x;
    int t = row >> 7, b = row & 127;
    int token = tok[b * TSEQ + t];
    float4 v = ((const float4*)(emb + (size_t)token * EMB))[threadIdx.x];
    size_t idx = (size_t)row * EMB + threadIdx.x * 4;
    bsplit2(g_ah, g_al, idx,     make_float2(v.x, v.y));
    bsplit2(g_ah, g_al, idx + 2, make_float2(v.z, v.w));
}

__global__ void init_h(const float* __restrict__ ihs) {
    int gi = blockIdx.x * blockDim.x + threadIdx.x;
    if (gi == 0) {                 // per-launch reset (graph replays reuse globals)
        g_ticket = 0;
        g_tdone = 0;
        g_recdone = 0;
    }
    int i = gi * 2;
    if (i < BH) {
        float2 a = *(const float2*)&ihs[i];
        float2 b = *(const float2*)&ihs[BH + i];
        *(float2*)&g_h0buf[i] = a;
        *(float2*)&g_h1buf[i] = b;
        bsplit2(g_h0h, g_h0l, i, a);
        bsplit2(g_h1h, g_h1l, i, b);
    }
}

__global__ void concat_bias(const float* __restrict__ bu, const float* __restrict__ br,
                            const float* __restrict__ bc) {
    int i = blockIdx.x * blockDim.x + threadIdx.x;
    if (i < 1024) {
        g_bias3[i]        = bu[i];
        g_bias3[1024 + i] = br[i];
        g_bias3[2048 + i] = bc[i];
    }
}

__global__ void state_out(float* __restrict__ out, long long out_size) {
    long long i = (long long)blockIdx.x * blockDim.x + threadIdx.x;
    long long base = (long long)BATCH * TSEQ * VOCAB;
    if (i < BH) {
        if (base + i < out_size)      out[base + i]      = g_h0buf[i];
        if (base + BH + i < out_size) out[base + BH + i] = g_h1buf[i];
    }
}

__global__ void tconv(const float* __restrict__ W, int ldw, int N, int ldo,
                      bf16* __restrict__ th, bf16* __restrict__ tl) {
    __shared__ float t[32][33];
    int n0 = blockIdx.x * 32, k0 = blockIdx.y * 32;
    int tx = threadIdx.x, ty = threadIdx.y;
    #pragma unroll
    for (int r = 0; r < 4; ++r) {
        int k = k0 + ty + r * 8, n = n0 + tx;
        t[ty + r * 8][tx] = (n < N) ? W[(size_t)k * ldw + n] : 0.f;
    }
    __syncthreads();
    #pragma unroll
    for (int r = 0; r < 4; ++r) {
        int n = n0 + ty + r * 8, k = k0 + tx;
        float x = t[tx][ty + r * 8];
        bf16 hh = __float2bfloat16(x);
        th[(size_t)n * ldo + k] = hh;
        tl[(size_t)n * ldo + k] = __float2bfloat16(x - __bfloat162float(hh));
    }
}

// ---------------- shared GEMM tile body (256 thr, 8 warps, 64x32 warp tile) ----------------
#define MM_LD 40
#define MM_MS (128*MM_LD)
#define MM_STG (4*MM_MS)

// A via .cg (written in-launch), B via .ca if BCA
template<int BCA>
__device__ __forceinline__ void tile_body(
    const bf16* Ah, const bf16* Al, size_t a_rowbase, int a_ld, int akoff,
    const bf16* Bh, const bf16* Bl, int n0, int b_ld, int bkoff,
    int kchunks, float acc[4][4][4], bf16* sm)
{
    const int tid = threadIdx.x, w = tid >> 5, l = tid & 31;
    const int mw = (w >> 2) * 64, nw = (w & 3) * 32;
    const unsigned sbase = smem_u32(sm);

    #pragma unroll
    for (int i = 0; i < 4; ++i)
        #pragma unroll
        for (int j = 0; j < 4; ++j)
            #pragma unroll
            for (int q = 0; q < 4; ++q) acc[i][j][q] = 0.f;

    auto stage_load = [&](int c, int s) {
        int kc = c * 32;
        unsigned sb = sbase + (unsigned)(s * MM_STG) * 2;
        #pragma unroll
        for (int l2 = 0; l2 < 2; ++l2) {
            int u = tid + l2 * 256;
            int row = u >> 2, q = u & 3;
            unsigned soff = (unsigned)(row * MM_LD + q * 8) * 2;
            size_t ga = a_rowbase + (size_t)row * a_ld + akoff + kc + q * 8;
            size_t gb = (size_t)(n0 + row) * b_ld + bkoff + kc + q * 8;
            cpg16(sb + 0 * MM_MS * 2 + soff, Ah + ga);
            cpg16(sb + 1 * MM_MS * 2 + soff, Al + ga);
            if (BCA) {
                cpa16(sb + 2 * MM_MS * 2 + soff, Bh + gb);
                cpa16(sb + 3 * MM_MS * 2 + soff, Bl + gb);
            } else {
                cpg16(sb + 2 * MM_MS * 2 + soff, Bh + gb);
                cpg16(sb + 3 * MM_MS * 2 + soff, Bl + gb);
            }
        }
    };

    stage_load(0, 0);
    asm volatile("cp.async.commit_group;" ::: "memory");
    const int ldrow = ((l >> 3) & 1) * 8 + (l & 7);
    const int ldcol = (l >> 4) * 8;

    for (int c = 0; c < kchunks; ++c) {
        if (c + 1 < kchunks) {
            stage_load(c + 1, (c + 1) & 1);
            asm volatile("cp.async.commit_group;" ::: "memory");
            asm volatile("cp.async.wait_group 1;" ::: "memory");
        } else {
            asm volatile("cp.async.wait_group 0;" ::: "memory");
        }
        __syncthreads();
        unsigned sb = sbase + (unsigned)((c & 1) * MM_STG) * 2;
        #pragma unroll
        for (int kk = 0; kk < 2; ++kk) {
            unsigned aH[4][4], aL[4][4], bH[4][2], bL[4][2];
            #pragma unroll
            for (int mt = 0; mt < 4; ++mt) {
                int r = mw + mt * 16 + ldrow;
                unsigned ad = sb + (unsigned)(r * MM_LD + kk * 16 + ldcol) * 2;
                ldsm4(aH[mt], ad);
                ldsm4(aL[mt], ad + MM_MS * 2);
            }
            #pragma unroll
            for (int p = 0; p < 2; ++p) {
                int r = nw + p * 16 + ldrow;
                unsigned bd = sb + (unsigned)(2 * MM_MS + r * MM_LD + kk * 16 + ldcol) * 2;
                unsigned t0[4], t1[4];
                ldsm4(t0, bd);
                ldsm4(t1, bd + MM_MS * 2);
                bH[2*p][0] = t0[0]; bH[2*p][1] = t0[2];
                bH[2*p+1][0] = t0[1]; bH[2*p+1][1] = t0[3];
                bL[2*p][0] = t1[0]; bL[2*p][1] = t1[2];
                bL[2*p+1][0] = t1[1]; bL[2*p+1][1] = t1[3];
            }
            #pragma unroll
            for (int mt = 0; mt < 4; ++mt)
                #pragma unroll
                for (int nt = 0; nt < 4; ++nt) {
                    mma16816(acc[mt][nt], aH[mt], bH[nt][0], bH[nt][1]);
                    mma16816(acc[mt][nt], aH[mt], bL[nt][0], bL[nt][1]);
                    mma16816(acc[mt][nt], aL[mt], bH[nt][0], bH[nt][1]);
                }
        }
        __syncthreads();
    }
}

// ---------------- standalone GEMM (pre MODE 0; trailing logits MODE 1 w/ ticket skip) ----------------
template<int MODE>
__global__ __launch_bounds__(256, 2)
void mma_gemm(const bf16* __restrict__ Ah, const bf16* __restrict__ Al,
              const bf16* __restrict__ Bh, const bf16* __restrict__ Bl,
              const float* __restrict__ bias, float* __restrict__ C, int N)
{
    extern __shared__ __align__(16) bf16 sm[];
    if (MODE == 1) {   // skip tiles already done by in-recurrence workers
        unsigned j = (unsigned)(blockIdx.x * NT80 + blockIdx.y);
        if (j < *(volatile unsigned*)&g_ticket) return;
    }
    const int tid = threadIdx.x, w = tid >> 5, l = tid & 31;
    const int m0 = blockIdx.x * 128, n0 = blockIdx.y * 128;
    const int mw = (w >> 2) * 64, nw = (w & 3) * 32;

    float acc[4][4][4];
    tile_body<1>(Ah, Al, (size_t)m0 * 1024, 1024, 0, Bh, Bl, n0, 1024, 0, 32, acc, sm);

    int g = l >> 2, tg = l & 3;
    #pragma unroll
    for (int mt = 0; mt < 4; ++mt) {
        int r0 = m0 + mw + mt * 16 + g;
        int r1 = r0 + 8;
        float *crow0, *crow1;
        if (MODE == 0) {
            crow0 = C + (size_t)r0 * N;
            crow1 = C + (size_t)r1 * N;
        } else {
            crow0 = C + ((size_t)(r0 & 127) * TSEQ + (r0 >> 7)) * N;
            crow1 = C + ((size_t)(r1 & 127) * TSEQ + (r1 >> 7)) * N;
        }
        #pragma unroll
        for (int nt = 0; nt < 4; ++nt) {
            int n = n0 + nw + nt * 8 + tg * 2;
            if (MODE == 0 || n < N) {
                float2 bv = *(const float2*)&bias[n];
                *(float2*)&crow0[n] = make_float2(acc[mt][nt][0] + bv.x, acc[mt][nt][1] + bv.y);
                *(float2*)&crow1[n] = make_float2(acc[mt][nt][2] + bv.x, acc[mt][nt][3] + bv.y);
            }
        }
    }
}

// ---------------- recurrence MMA tile ----------------
__device__ __noinline__ void rec_mma(
    const bf16* Ah, const bf16* Al, int akoff,
    const bf16* Bh, const bf16* Bl, int bkoff, int ldb,
    int n0, int kchunks, float* outp, int outW, bf16* sm)
{
    const int tid = threadIdx.x, w = tid >> 5, l = tid & 31;
    const int mw = (w >> 2) * 64, nw = (w & 3) * 32;
    float acc[4][4][4];
    tile_body<0>(Ah, Al, 0, 1024, akoff, Bh, Bl, n0, ldb, bkoff, kchunks, acc, sm);

    int g = l >> 2, tg = l & 3;
    #pragma unroll
    for (int mt = 0; mt < 4; ++mt) {
        int r0 = mw + mt * 16 + g;
        int r1 = r0 + 8;
        #pragma unroll
        for (int nt = 0; nt < 4; ++nt) {
            int n = n0 + nw + nt * 8 + tg * 2;
            *(float2*)&outp[(size_t)r0 * outW + n] = make_float2(acc[mt][nt][0], acc[mt][nt][1]);
            *(float2*)&outp[(size_t)r1 * outW + n] = make_float2(acc[mt][nt][2], acc[mt][nt][3]);
        }
    }
}

// ---------------- in-recurrence logits worker tile ----------------
__device__ __noinline__ void logits_tile(
    int m0, int n0, const float* __restrict__ bias, float* __restrict__ C, bf16* sm)
{
    const int tid = threadIdx.x, w = tid >> 5, l = tid & 31;
    const int mw = (w >> 2) * 64, nw = (w & 3) * 32;
    float acc[4][4][4];
    tile_body<1>(g_ah, g_al, (size_t)m0 * 1024, 1024, 0, g_bth, g_btl, n0, 1024, 0, 32, acc, sm);

    int g = l >> 2, tg = l & 3;
    #pragma unroll
    for (int mt = 0; mt < 4; ++mt) {
        int r0 = m0 + mw + mt * 16 + g;
        int r1 = r0 + 8;
        float* crow0 = C + ((size_t)(r0 & 127) * TSEQ + (r0 >> 7)) * VOCAB;
        float* crow1 = C + ((size_t)(r1 & 127) * TSEQ + (r1 >> 7)) * VOCAB;
        #pragma unroll
        for (int nt = 0; nt < 4; ++nt) {
            int n = n0 + nw + nt * 8 + tg * 2;
            if (n < VOCAB) {
                float2 bv = *(const float2*)&bias[n];
                *(float2*)&crow0[n] = make_float2(acc[mt][nt][0] + bv.x, acc[mt][nt][1] + bv.y);
                *(float2*)&crow1[n] = make_float2(acc[mt][nt][2] + bv.x, acc[mt][nt][3] + bv.y);
            }
        }
    }
}

// ---------------- persistent recurrence (+ logits workers) ----------------
struct RecParams {
    const float *bu1, *br1, *bc1;
    const float *bout;
    float *out;
};

__device__ __forceinline__ void grid_barrier(unsigned& sense) {
    __syncthreads();
    if (threadIdx.x == 0) {
        unsigned next = sense ^ 1u;
        __threadfence();
        if (atomicAdd(&g_barcnt, 1u) == RECB - 1) {
            g_barcnt = 0;
            __threadfence();
            g_barsense = next;
        } else {
            while (g_barsense != next) __nanosleep(32);
        }
    }
    sense ^= 1u;
    __syncthreads();
}

__global__ __launch_bounds__(256, 1)
void recurrence_kernel(RecParams P)
{
    extern __shared__ __align__(16) bf16 sm[];
    const int bid = blockIdx.x;
    const int tid = threadIdx.x;

    // ---- worker CTAs: stream logits tiles as h1(t) becomes available ----
    // CTA-uniform protocol: tid0 makes the grab/exit decision, broadcast via smem.
    if (bid >= RECB) {
        __shared__ unsigned s_job;
        for (;;) {
            if (tid == 0) {
                unsigned j = 0xFFFFFFFFu;                 // uniform exit sentinel
                if (!g_recdone) j = atomicAdd(&g_ticket, 1u);
                s_job = j;
            }
            __syncthreads();
            unsigned j = s_job;
            __syncthreads();
            if (j >= NJOBS) break;                        // uniform across CTA
            int t = (int)(j / NT80), n0 = (int)(j % NT80) * 128;
            if (tid == 0) {
                while (g_tdone <= (unsigned)t) __nanosleep(64);
            }
            __syncthreads();
            logits_tile(t * 128, n0, P.bout, P.out, sm);
        }
        return;
    }

    // ---- recurrence CTAs ----
    unsigned sense = 0;
    for (int t = 0; t < TSEQ; ++t) {
        const int cur = t & 1, nxt = cur ^ 1;
        const float* xp = g_xp + (size_t)t * BATCH * XP3;
        float* h0c = g_h0buf + (size_t)cur * BH;
        float* h0n = g_h0buf + (size_t)nxt * BH;
        float* h1c = g_h1buf + (size_t)cur * BH;
        float* h1n = g_h1buf + (size_t)nxt * BH;
        bf16 *h0ch = g_h0h + (size_t)cur * BH, *h0cl = g_h0l + (size_t)cur * BH;
        bf16 *h0nh = g_h0h + (size_t)nxt * BH, *h0nl = g_h0l + (size_t)nxt * BH;
        bf16 *h1ch = g_h1h + (size_t)cur * BH, *h1cl = g_h1l + (size_t)cur * BH;
        bf16 *h1nh = g_h1h + (size_t)nxt * BH, *h1nl = g_h1l + (size_t)nxt * BH;

        // Phase A: layer0 u,r h-part -> pA
        {
            int gg = bid >> 6, ks = bid & 7, nt = (bid >> 3) & 7;
            rec_mma(h0ch, h0cl, ks * 128,
                    g_wt0h + (size_t)gg * 1024 * 1024, g_wt0l + (size_t)gg * 1024 * 1024,
                    ks * 128, 1024, nt * 128, 4,
                    g_pA + (size_t)ks * 128 * 2048 + gg * 1024, 2048, sm);
        }
        grid_barrier(sense);

        // ACT A: rh0 = sig(xr + sum pA[r]) * h0c
        for (int i = bid * 256 + tid; i < BH / 2; i += RECB * 256) {
            size_t idx = (size_t)i * 2;
            int m = (int)(idx >> 10), n = (int)(idx & 1023);
            float2 s = *(const float2*)&xp[(size_t)m * XP3 + 1024 + n];
            #pragma unroll
            for (int p = 0; p < 8; ++p) {
                float2 v = __ldcg((const float2*)&g_pA[((size_t)p * 128 + m) * 2048 + 1024 + n]);
                s.x += v.x; s.y += v.y;
            }
            float2 h = __ldcg((const float2*)&h0c[idx]);
            bsplit2(g_rh0h, g_rh0l, idx, make_float2(sigf(s.x) * h.x, sigf(s.y) * h.y));
        }
        grid_barrier(sense);

        // Phase B: layer0 candidate -> pB
        {
            int ks = bid & 15, nt = bid >> 4;
            rec_mma(g_rh0h, g_rh0l, ks * 64,
                    g_wt0h + (size_t)2 * 1024 * 1024, g_wt0l + (size_t)2 * 1024 * 1024,
                    ks * 64, 1024, nt * 128, 2,
                    g_pB + (size_t)ks * 128 * 1024, 1024, sm);
        }
        grid_barrier(sense);

        // ACT B: h0n = u*h0c + (1-u)*tanh(xc + sum pB)
        for (int i = bid * 256 + tid; i < BH / 2; i += RECB * 256) {
            size_t idx = (size_t)i * 2;
            int m = (int)(idx >> 10), n = (int)(idx & 1023);
            float2 su = *(const float2*)&xp[(size_t)m * XP3 + n];
            #pragma unroll
            for (int p = 0; p < 8; ++p) {
                float2 v = __ldcg((const float2*)&g_pA[((size_t)p * 128 + m) * 2048 + n]);
                su.x += v.x; su.y += v.y;
            }
            float2 sc = *(const float2*)&xp[(size_t)m * XP3 + 2048 + n];
            #pragma unroll
            for (int p = 0; p < 16; ++p) {
                float2 v = __ldcg((const float2*)&g_pB[((size_t)p * 128 + m) * 1024 + n]);
                sc.x += v.x; sc.y += v.y;
            }
            float2 h = __ldcg((const float2*)&h0c[idx]);
            float ux = sigf(su.x), uy = sigf(su.y);
            float2 o = make_float2(ux * h.x + (1.f - ux) * tanhf(sc.x),
                                   uy * h.y + (1.f - uy) * tanhf(sc.y));
            *(float2*)&h0n[idx] = o;
            bsplit2(h0nh, h0nl, idx, o);
        }
        grid_barrier(sense);

        // Phase C: layer1 u,r over [h0n | h1c] -> pC
        {
            int gg = bid >> 6, ks = bid & 7, nt = (bid >> 3) & 7;
            int koff = ks * 256;
            const bf16* ah = (koff < 1024) ? h0nh : h1ch;
            const bf16* al = (koff < 1024) ? h0nl : h1cl;
            rec_mma(ah, al, koff & 1023,
                    g_wt1h + (size_t)gg * 1024 * 2048, g_wt1l + (size_t)gg * 1024 * 2048,
                    koff, 2048, nt * 128, 8,
                    g_pC + (size_t)ks * 128 * 2048 + gg * 1024, 2048, sm);
        }
        grid_barrier(sense);

        // ACT C: rh1 = sig(br1 + sum pC[r]) * h1c
        for (int i = bid * 256 + tid; i < BH / 2; i += RECB * 256) {
            size_t idx = (size_t)i * 2;
            int m = (int)(idx >> 10), n = (int)(idx & 1023);
            float2 s = *(const float2*)&P.br1[n];
            #pragma unroll
            for (int p = 0; p < 8; ++p) {
                float2 v = __ldcg((const float2*)&g_pC[((size_t)p * 128 + m) * 2048 + 1024 + n]);
                s.x += v.x; s.y += v.y;
            }
            float2 h = __ldcg((const float2*)&h1c[idx]);
            bsplit2(g_rh1h, g_rh1l, idx, make_float2(sigf(s.x) * h.x, sigf(s.y) * h.y));
        }
        grid_barrier(sense);

        // Phase D: layer1 candidate over [h0n | rh1] -> pD
        {
            int ks = bid & 15, nt = bid >> 4;
            int koff = ks * 128;
            const bf16* ah = (koff < 1024) ? h0nh : g_rh1h;
            const bf16* al = (koff < 1024) ? h0nl : g_rh1l;
            rec_mma(ah, al, koff & 1023,
                    g_wt1h + (size_t)2 * 1024 * 2048, g_wt1l + (size_t)2 * 1024 * 2048,
                    koff, 2048, nt * 128, 4,
                    g_pD + (size_t)ks * 128 * 1024, 1024, sm);
        }
        grid_barrier(sense);

        // ACT D: h1n; bf16 splits into logits A buffers
        {
            bf16* seqh = g_ah + (size_t)t * BH;
            bf16* seql = g_al + (size_t)t * BH;
            for (int i = bid * 256 + tid; i < BH / 2; i += RECB * 256) {
                size_t idx = (size_t)i * 2;
                int m = (int)(idx >> 10), n = (int)(idx & 1023);
                float2 su = *(const float2*)&P.bu1[n];
                #pragma unroll
                for (int p = 0; p < 8; ++p) {
                    float2 v = __ldcg((const float2*)&g_pC[((size_t)p * 128 + m) * 2048 + n]);
                    su.x += v.x; su.y += v.y;
                }
                float2 sc = *(const float2*)&P.bc1[n];
                #pragma unroll
                for (int p = 0; p < 16; ++p) {
                    float2 v = __ldcg((const float2*)&g_pD[((size_t)p * 128 + m) * 1024 + n]);
                    sc.x += v.x; sc.y += v.y;
                }
                float2 h = __ldcg((const float2*)&h1c[idx]);
                float ux = sigf(su.x), uy = sigf(su.y);
                float2 o = make_float2(ux * h.x + (1.f - ux) * tanhf(sc.x),
                                       uy * h.y + (1.f - uy) * tanhf(sc.y));
                *(float2*)&h1n[idx] = o;
                bsplit2(seqh, seql, idx, o);
                bsplit2(h1nh, h1nl, idx, o);
            }
        }
        grid_barrier(sense);

        // publish step t to logits workers (barrier above ordered the writes)
        if (bid == 0 && tid == 0) {
            __threadfence();
            g_tdone = (unsigned)(t + 1);
        }
    }

    if (bid == 0 && tid == 0) {
        __threadfence();
        g_recdone = 1u;
    }
}

// ---------------- host orchestration ----------------
extern "C" void kernel_launch(void* const* d_in, const int* in_sizes, int n_in,
                              void* d_out, int out_size)
{
    const int*   tok  = (const int*)  d_in[0];
    const float* ihs  = (const float*)d_in[1];
    const float* emb  = (const float*)d_in[2];
    const float* Wout = (const float*)d_in[3];
    const float* bout = (const float*)d_in[4];
    const float* wu0  = (const float*)d_in[5];
    const float* bu0  = (const float*)d_in[6];
    const float* wr0  = (const float*)d_in[7];
    const float* br0  = (const float*)d_in[8];
    const float* wc0  = (const float*)d_in[9];
    const float* bc0  = (const float*)d_in[10];
    const float* wu1  = (const float*)d_in[11];
    const float* bu1  = (const float*)d_in[12];
    const float* wr1  = (const float*)d_in[13];
    const float* br1  = (const float*)d_in[14];
    const float* wc1  = (const float*)d_in[15];
    const float* bc1  = (const float*)d_in[16];

    float *p_xp, *p_bias3;
    bf16 *p_ah, *p_al, *p_bth, *p_btl, *p_wt0h, *p_wt0l, *p_wt1h, *p_wt1l;
    cudaGetSymbolAddress((void**)&p_xp,    g_xp);
    cudaGetSymbolAddress((void**)&p_bias3, g_bias3);
    cudaGetSymbolAddress((void**)&p_ah,  g_ah);
    cudaGetSymbolAddress((void**)&p_al,  g_al);
    cudaGetSymbolAddress((void**)&p_bth, g_bth);
    cudaGetSymbolAddress((void**)&p_btl, g_btl);
    cudaGetSymbolAddress((void**)&p_wt0h, g_wt0h);
    cudaGetSymbolAddress((void**)&p_wt0l, g_wt0l);
    cudaGetSymbolAddress((void**)&p_wt1h, g_wt1h);
    cudaGetSymbolAddress((void**)&p_wt1l, g_wt1l);

    const int MM_SMEM = 2 * MM_STG * 2;   // 81920 B
    cudaFuncSetAttribute(mma_gemm<0>, cudaFuncAttributeMaxDynamicSharedMemorySize, MM_SMEM);
    cudaFuncSetAttribute(mma_gemm<1>, cudaFuncAttributeMaxDynamicSharedMemorySize, MM_SMEM);
    cudaFuncSetAttribute(recurrence_kernel, cudaFuncAttributeMaxDynamicSharedMemorySize, MM_SMEM);

    // 1) gather embeddings + bf16 split
    gather_kernel<<<TSEQ * BATCH, 256>>>(tok, emb);

    // 2) fused pre: one GEMM for all 3 layer-0 x-projections (N = 3072)
    dim3 tb(32, 8);
    tconv<<<dim3(32, 32), tb>>>(wu0, HID, HID, 1024, p_bth,               p_btl);
    tconv<<<dim3(32, 32), tb>>>(wr0, HID, HID, 1024, p_bth + 1024*1024,   p_btl + 1024*1024);
    tconv<<<dim3(32, 32), tb>>>(wc0, HID, HID, 1024, p_bth + 2*1024*1024, p_btl + 2*1024*1024);
    concat_bias<<<4, 256>>>(bu0, br0, bc0);
    mma_gemm<0><<<dim3(64, XP3 / 128), 256, MM_SMEM>>>(p_ah, p_al, p_bth, p_btl,
                                                        p_bias3, p_xp, XP3);

    // 3) logits weights — FULL transpose grid (NPAD/32 = 320 n-tiles, was the R12/R13 bug)
    tconv<<<dim3(NPAD / 32, 32), tb>>>(Wout, VOCAB, VOCAB, 1024, p_bth, p_btl);

    // 4) recurrence weight transposes
    const size_t EH = (size_t)EMB * HID;
    tconv<<<dim3(32, 32), tb>>>(wu0 + EH, HID, HID, 1024, p_wt0h,               p_wt0l);
    tconv<<<dim3(32, 32), tb>>>(wr0 + EH, HID, HID, 1024, p_wt0h + 1024*1024,   p_wt0l + 1024*1024);
    tconv<<<dim3(32, 32), tb>>>(wc0 + EH, HID, HID, 1024, p_wt0h + 2*1024*1024, p_wt0l + 2*1024*1024);
    tconv<<<dim3(32, 64), tb>>>(wu1, HID, HID, 2048, p_wt1h,               p_wt1l);
    tconv<<<dim3(32, 64), tb>>>(wr1, HID, HID, 2048, p_wt1h + 1024*2048,   p_wt1l + 1024*2048);
    tconv<<<dim3(32, 64), tb>>>(wc1, HID, HID, 2048, p_wt1h + 2*1024*2048, p_wt1l + 2*1024*2048);

    // 5) initial hidden state + per-launch counter reset
    init_h<<<(BH / 2 + 255) / 256, 256>>>(ihs);

    // 6) persistent recurrence; CTAs 128..147 stream logits tiles concurrently
    RecParams P{bu1, br1, bc1, bout, (float*)d_out};
    recurrence_kernel<<<NBLK, 256, MM_SMEM>>>(P);

    // 7) remaining logits tiles (skips j < g_ticket done in-recurrence)
    mma_gemm<1><<<dim3(64, NT80), 256, MM_SMEM>>>(p_ah, p_al, p_bth, p_btl,
                                                   bout, (float*)d_out, VOCAB);

    // 8) final states
    state_out<<<(BH + 255) / 256, 256>>>((float*)d_out, (long long)out_size);
}

// round 15
// speedup vs baseline: 1.1227x; 1.0537x over previous
#include <cuda_runtime.h>
#include <cuda_bf16.h>
#include <math.h>

#define BATCH 128
#define TSEQ  64
#define VOCAB 10000
#define EMB   1024
#define HID   1024
#define GRID  296               // 2 CTAs per SM: 128 recurrence + 168 logits workers
#define RECB  128               // CTAs participating in recurrence phases
#define BH    (BATCH*HID)
#define NPAD  10240
#define NT80  (NPAD/128)        // 80 logits n-tiles
#define NJOBS (TSEQ*NT80)       // 5120 logits tiles
#define XP3   3072

typedef unsigned long long ull;
typedef __nv_bfloat16 bf16;

__device__ __forceinline__ float sigf(float x) { return 1.f / (1.f + expf(-x)); }

// ---------------- mma.sync helpers ----------------
__device__ __forceinline__ unsigned smem_u32(const void* p) {
    unsigned a;
    asm("{ .reg .u64 t; cvta.to.shared.u64 t, %1; cvt.u32.u64 %0, t; }" : "=r"(a) : "l"(p));
    return a;
}
__device__ __forceinline__ void ldsm4(unsigned* r, unsigned a) {
    asm volatile("ldmatrix.sync.aligned.m8n8.x4.shared.b16 {%0,%1,%2,%3}, [%4];"
                 : "=r"(r[0]), "=r"(r[1]), "=r"(r[2]), "=r"(r[3]) : "r"(a));
}
__device__ __forceinline__ void mma16816(float* c, const unsigned* a, unsigned b0, unsigned b1) {
    asm volatile("mma.sync.aligned.m16n8k16.row.col.f32.bf16.bf16.f32 "
                 "{%0,%1,%2,%3}, {%4,%5,%6,%7}, {%8,%9}, {%0,%1,%2,%3};"
                 : "+f"(c[0]), "+f"(c[1]), "+f"(c[2]), "+f"(c[3])
                 : "r"(a[0]), "r"(a[1]), "r"(a[2]), "r"(a[3]), "r"(b0), "r"(b1));
}
__device__ __forceinline__ void cpa16(unsigned saddr, const void* g) {
    asm volatile("cp.async.ca.shared.global [%0], [%1], 16;" :: "r"(saddr), "l"(g));
}
__device__ __forceinline__ void cpg16(unsigned saddr, const void* g) {
    asm volatile("cp.async.cg.shared.global [%0], [%1], 16;" :: "r"(saddr), "l"(g));
}

// ---------------- device scratch ----------------
__device__ float g_xp[TSEQ*BATCH*XP3];
__device__ float g_h0buf[2*BH];
__device__ float g_h1buf[2*BH];
__device__ float g_pA[8*128*2048];
__device__ float g_pB[16*128*1024];
__device__ float g_pC[8*128*2048];
__device__ float g_pD[16*128*1024];
__device__ float g_bias3[XP3];
__device__ bf16 g_ah[TSEQ*BH];           // emb splits, then h1seq splits
__device__ bf16 g_al[TSEQ*BH];
__device__ bf16 g_bth[NPAD*1024];
__device__ bf16 g_btl[NPAD*1024];
__device__ bf16 g_wt0h[3*1024*1024];
__device__ bf16 g_wt0l[3*1024*1024];
__device__ bf16 g_wt1h[3*1024*2048];
__device__ bf16 g_wt1l[3*1024*2048];
__device__ bf16 g_h0h[2*BH], g_h0l[2*BH];
__device__ bf16 g_h1h[2*BH], g_h1l[2*BH];
__device__ bf16 g_rh0h[BH], g_rh0l[BH];
__device__ bf16 g_rh1h[BH], g_rh1l[BH];
__device__ unsigned g_barcnt;
__device__ volatile unsigned g_barsense;
__device__ unsigned g_ticket;            // next logits tile to grab
__device__ volatile unsigned g_tdone;    // steps with h1 published
__device__ volatile unsigned g_recdone;  // recurrence finished flag

__device__ __forceinline__ void bsplit2(bf16* bh, bf16* bl, size_t idx, float2 v) {
    bf16 h0 = __float2bfloat16(v.x), h1 = __float2bfloat16(v.y);
    bf16 l0 = __float2bfloat16(v.x - __bfloat162float(h0));
    bf16 l1 = __float2bfloat16(v.y - __bfloat162float(h1));
    *(__nv_bfloat162*)(bh + idx) = __halves2bfloat162(h0, h1);
    *(__nv_bfloat162*)(bl + idx) = __halves2bfloat162(l0, l1);
}

// ---------------- small kernels ----------------
__global__ void gather_kernel(const int* __restrict__ tok, const float* __restrict__ emb) {
    int row = blockIdx.x;
    int t = row >> 7, b = row & 127;
    int token = tok[b * TSEQ + t];
    float4 v = ((const float4*)(emb + (size_t)token * EMB))[threadIdx.x];
    size_t idx = (size_t)row * EMB + threadIdx.x * 4;
    bsplit2(g_ah, g_al, idx,     make_float2(v.x, v.y));
    bsplit2(g_ah, g_al, idx + 2, make_float2(v.z, v.w));
}

__global__ void init_h(const float* __restrict__ ihs) {
    int gi = blockIdx.x * blockDim.x + threadIdx.x;
    if (gi == 0) {                 // per-launch reset (graph replays reuse globals)
        g_ticket = 0;
        g_tdone = 0;
        g_recdone = 0;
    }
    int i = gi * 2;
    if (i < BH) {
        float2 a = *(const float2*)&ihs[i];
        float2 b = *(const float2*)&ihs[BH + i];
        *(float2*)&g_h0buf[i] = a;
        *(float2*)&g_h1buf[i] = b;
        bsplit2(g_h0h, g_h0l, i, a);
        bsplit2(g_h1h, g_h1l, i, b);
    }
}

__global__ void concat_bias(const float* __restrict__ bu, const float* __restrict__ br,
                            const float* __restrict__ bc) {
    int i = blockIdx.x * blockDim.x + threadIdx.x;
    if (i < 1024) {
        g_bias3[i]        = bu[i];
        g_bias3[1024 + i] = br[i];
        g_bias3[2048 + i] = bc[i];
    }
}

__global__ void state_out(float* __restrict__ out, long long out_size) {
    long long i = (long long)blockIdx.x * blockDim.x + threadIdx.x;
    long long base = (long long)BATCH * TSEQ * VOCAB;
    if (i < BH) {
        if (base + i < out_size)      out[base + i]      = g_h0buf[i];
        if (base + BH + i < out_size) out[base + BH + i] = g_h1buf[i];
    }
}

__global__ void tconv(const float* __restrict__ W, int ldw, int N, int ldo,
                      bf16* __restrict__ th, bf16* __restrict__ tl) {
    __shared__ float t[32][33];
    int n0 = blockIdx.x * 32, k0 = blockIdx.y * 32;
    int tx = threadIdx.x, ty = threadIdx.y;
    #pragma unroll
    for (int r = 0; r < 4; ++r) {
        int k = k0 + ty + r * 8, n = n0 + tx;
        t[ty + r * 8][tx] = (n < N) ? W[(size_t)k * ldw + n] : 0.f;
    }
    __syncthreads();
    #pragma unroll
    for (int r = 0; r < 4; ++r) {
        int n = n0 + ty + r * 8, k = k0 + tx;
        float x = t[tx][ty + r * 8];
        bf16 hh = __float2bfloat16(x);
        th[(size_t)n * ldo + k] = hh;
        tl[(size_t)n * ldo + k] = __float2bfloat16(x - __bfloat162float(hh));
    }
}

// ---------------- shared GEMM tile body (256 thr, 8 warps, 64x32 warp tile) ----------------
#define MM_LD 40
#define MM_MS (128*MM_LD)
#define MM_STG (4*MM_MS)

// A via .cg (written in-launch), B via .ca if BCA
template<int BCA>
__device__ __forceinline__ void tile_body(
    const bf16* Ah, const bf16* Al, size_t a_rowbase, int a_ld, int akoff,
    const bf16* Bh, const bf16* Bl, int n0, int b_ld, int bkoff,
    int kchunks, float acc[4][4][4], bf16* sm)
{
    const int tid = threadIdx.x, w = tid >> 5, l = tid & 31;
    const int mw = (w >> 2) * 64, nw = (w & 3) * 32;
    const unsigned sbase = smem_u32(sm);

    #pragma unroll
    for (int i = 0; i < 4; ++i)
        #pragma unroll
        for (int j = 0; j < 4; ++j)
            #pragma unroll
            for (int q = 0; q < 4; ++q) acc[i][j][q] = 0.f;

    auto stage_load = [&](int c, int s) {
        int kc = c * 32;
        unsigned sb = sbase + (unsigned)(s * MM_STG) * 2;
        #pragma unroll
        for (int l2 = 0; l2 < 2; ++l2) {
            int u = tid + l2 * 256;
            int row = u >> 2, q = u & 3;
            unsigned soff = (unsigned)(row * MM_LD + q * 8) * 2;
            size_t ga = a_rowbase + (size_t)row * a_ld + akoff + kc + q * 8;
            size_t gb = (size_t)(n0 + row) * b_ld + bkoff + kc + q * 8;
            cpg16(sb + 0 * MM_MS * 2 + soff, Ah + ga);
            cpg16(sb + 1 * MM_MS * 2 + soff, Al + ga);
            if (BCA) {
                cpa16(sb + 2 * MM_MS * 2 + soff, Bh + gb);
                cpa16(sb + 3 * MM_MS * 2 + soff, Bl + gb);
            } else {
                cpg16(sb + 2 * MM_MS * 2 + soff, Bh + gb);
                cpg16(sb + 3 * MM_MS * 2 + soff, Bl + gb);
            }
        }
    };

    stage_load(0, 0);
    asm volatile("cp.async.commit_group;" ::: "memory");
    const int ldrow = ((l >> 3) & 1) * 8 + (l & 7);
    const int ldcol = (l >> 4) * 8;

    for (int c = 0; c < kchunks; ++c) {
        if (c + 1 < kchunks) {
            stage_load(c + 1, (c + 1) & 1);
            asm volatile("cp.async.commit_group;" ::: "memory");
            asm volatile("cp.async.wait_group 1;" ::: "memory");
        } else {
            asm volatile("cp.async.wait_group 0;" ::: "memory");
        }
        __syncthreads();
        unsigned sb = sbase + (unsigned)((c & 1) * MM_STG) * 2;
        #pragma unroll
        for (int kk = 0; kk < 2; ++kk) {
            unsigned aH[4][4], aL[4][4], bH[4][2], bL[4][2];
            #pragma unroll
            for (int mt = 0; mt < 4; ++mt) {
                int r = mw + mt * 16 + ldrow;
                unsigned ad = sb + (unsigned)(r * MM_LD + kk * 16 + ldcol) * 2;
                ldsm4(aH[mt], ad);
                ldsm4(aL[mt], ad + MM_MS * 2);
            }
            #pragma unroll
            for (int p = 0; p < 2; ++p) {
                int r = nw + p * 16 + ldrow;
                unsigned bd = sb + (unsigned)(2 * MM_MS + r * MM_LD + kk * 16 + ldcol) * 2;
                unsigned t0[4], t1[4];
                ldsm4(t0, bd);
                ldsm4(t1, bd + MM_MS * 2);
                bH[2*p][0] = t0[0]; bH[2*p][1] = t0[2];
                bH[2*p+1][0] = t0[1]; bH[2*p+1][1] = t0[3];
                bL[2*p][0] = t1[0]; bL[2*p][1] = t1[2];
                bL[2*p+1][0] = t1[1]; bL[2*p+1][1] = t1[3];
            }
            #pragma unroll
            for (int mt = 0; mt < 4; ++mt)
                #pragma unroll
                for (int nt = 0; nt < 4; ++nt) {
                    mma16816(acc[mt][nt], aH[mt], bH[nt][0], bH[nt][1]);
                    mma16816(acc[mt][nt], aH[mt], bL[nt][0], bL[nt][1]);
                    mma16816(acc[mt][nt], aL[mt], bH[nt][0], bH[nt][1]);
                }
        }
        __syncthreads();
    }
}

// ---------------- standalone GEMM (pre MODE 0; trailing logits MODE 1 w/ ticket skip) ----------------
template<int MODE>
__global__ __launch_bounds__(256, 2)
void mma_gemm(const bf16* __restrict__ Ah, const bf16* __restrict__ Al,
              const bf16* __restrict__ Bh, const bf16* __restrict__ Bl,
              const float* __restrict__ bias, float* __restrict__ C, int N)
{
    extern __shared__ __align__(16) bf16 sm[];
    if (MODE == 1) {   // skip tiles already done by in-recurrence workers
        unsigned j = (unsigned)(blockIdx.x * NT80 + blockIdx.y);
        if (j < *(volatile unsigned*)&g_ticket) return;
    }
    const int tid = threadIdx.x, w = tid >> 5, l = tid & 31;
    const int m0 = blockIdx.x * 128, n0 = blockIdx.y * 128;
    const int mw = (w >> 2) * 64, nw = (w & 3) * 32;

    float acc[4][4][4];
    tile_body<1>(Ah, Al, (size_t)m0 * 1024, 1024, 0, Bh, Bl, n0, 1024, 0, 32, acc, sm);

    int g = l >> 2, tg = l & 3;
    #pragma unroll
    for (int mt = 0; mt < 4; ++mt) {
        int r0 = m0 + mw + mt * 16 + g;
        int r1 = r0 + 8;
        float *crow0, *crow1;
        if (MODE == 0) {
            crow0 = C + (size_t)r0 * N;
            crow1 = C + (size_t)r1 * N;
        } else {
            crow0 = C + ((size_t)(r0 & 127) * TSEQ + (r0 >> 7)) * N;
            crow1 = C + ((size_t)(r1 & 127) * TSEQ + (r1 >> 7)) * N;
        }
        #pragma unroll
        for (int nt = 0; nt < 4; ++nt) {
            int n = n0 + nw + nt * 8 + tg * 2;
            if (MODE == 0 || n < N) {
                float2 bv = *(const float2*)&bias[n];
                *(float2*)&crow0[n] = make_float2(acc[mt][nt][0] + bv.x, acc[mt][nt][1] + bv.y);
                *(float2*)&crow1[n] = make_float2(acc[mt][nt][2] + bv.x, acc[mt][nt][3] + bv.y);
            }
        }
    }
}

// ---------------- recurrence MMA tile ----------------
__device__ __noinline__ void rec_mma(
    const bf16* Ah, const bf16* Al, int akoff,
    const bf16* Bh, const bf16* Bl, int bkoff, int ldb,
    int n0, int kchunks, float* outp, int outW, bf16* sm)
{
    const int tid = threadIdx.x, w = tid >> 5, l = tid & 31;
    const int mw = (w >> 2) * 64, nw = (w & 3) * 32;
    float acc[4][4][4];
    tile_body<0>(Ah, Al, 0, 1024, akoff, Bh, Bl, n0, ldb, bkoff, kchunks, acc, sm);

    int g = l >> 2, tg = l & 3;
    #pragma unroll
    for (int mt = 0; mt < 4; ++mt) {
        int r0 = mw + mt * 16 + g;
        int r1 = r0 + 8;
        #pragma unroll
        for (int nt = 0; nt < 4; ++nt) {
            int n = n0 + nw + nt * 8 + tg * 2;
            *(float2*)&outp[(size_t)r0 * outW + n] = make_float2(acc[mt][nt][0], acc[mt][nt][1]);
            *(float2*)&outp[(size_t)r1 * outW + n] = make_float2(acc[mt][nt][2], acc[mt][nt][3]);
        }
    }
}

// ---------------- in-recurrence logits worker tile ----------------
__device__ __noinline__ void logits_tile(
    int m0, int n0, const float* __restrict__ bias, float* __restrict__ C, bf16* sm)
{
    const int tid = threadIdx.x, w = tid >> 5, l = tid & 31;
    const int mw = (w >> 2) * 64, nw = (w & 3) * 32;
    float acc[4][4][4];
    tile_body<1>(g_ah, g_al, (size_t)m0 * 1024, 1024, 0, g_bth, g_btl, n0, 1024, 0, 32, acc, sm);

    int g = l >> 2, tg = l & 3;
    #pragma unroll
    for (int mt = 0; mt < 4; ++mt) {
        int r0 = m0 + mw + mt * 16 + g;
        int r1 = r0 + 8;
        float* crow0 = C + ((size_t)(r0 & 127) * TSEQ + (r0 >> 7)) * VOCAB;
        float* crow1 = C + ((size_t)(r1 & 127) * TSEQ + (r1 >> 7)) * VOCAB;
        #pragma unroll
        for (int nt = 0; nt < 4; ++nt) {
            int n = n0 + nw + nt * 8 + tg * 2;
            if (n < VOCAB) {
                float2 bv = *(const float2*)&bias[n];
                *(float2*)&crow0[n] = make_float2(acc[mt][nt][0] + bv.x, acc[mt][nt][1] + bv.y);
                *(float2*)&crow1[n] = make_float2(acc[mt][nt][2] + bv.x, acc[mt][nt][3] + bv.y);
            }
        }
    }
}

// ---------------- persistent recurrence (+ logits workers), 2 CTAs/SM ----------------
struct RecParams {
    const float *bu1, *br1, *bc1;
    const float *bout;
    float *out;
};

__device__ __forceinline__ void grid_barrier(unsigned& sense) {
    __syncthreads();
    if (threadIdx.x == 0) {
        unsigned next = sense ^ 1u;
        __threadfence();
        if (atomicAdd(&g_barcnt, 1u) == RECB - 1) {
            g_barcnt = 0;
            __threadfence();
            g_barsense = next;
        } else {
            while (g_barsense != next) __nanosleep(32);
        }
    }
    sense ^= 1u;
    __syncthreads();
}

__global__ __launch_bounds__(256, 2)
void recurrence_kernel(RecParams P)
{
    extern __shared__ __align__(16) bf16 sm[];
    const int bid = blockIdx.x;
    const int tid = threadIdx.x;

    // ---- worker CTAs (168): stream logits tiles as h1(t) becomes available ----
    if (bid >= RECB) {
        __shared__ unsigned s_job;
        for (;;) {
            if (tid == 0) {
                unsigned j = 0xFFFFFFFFu;                 // uniform exit sentinel
                if (!g_recdone) j = atomicAdd(&g_ticket, 1u);
                s_job = j;
            }
            __syncthreads();
            unsigned j = s_job;
            __syncthreads();
            if (j >= NJOBS) break;                        // uniform across CTA
            int t = (int)(j / NT80), n0 = (int)(j % NT80) * 128;
            if (tid == 0) {
                while (g_tdone <= (unsigned)t) __nanosleep(64);
            }
            __syncthreads();
            logits_tile(t * 128, n0, P.bout, P.out, sm);
        }
        return;
    }

    // ---- recurrence CTAs (128) ----
    unsigned sense = 0;
    for (int t = 0; t < TSEQ; ++t) {
        const int cur = t & 1, nxt = cur ^ 1;
        const float* xp = g_xp + (size_t)t * BATCH * XP3;
        float* h0c = g_h0buf + (size_t)cur * BH;
        float* h0n = g_h0buf + (size_t)nxt * BH;
        float* h1c = g_h1buf + (size_t)cur * BH;
        float* h1n = g_h1buf + (size_t)nxt * BH;
        bf16 *h0ch = g_h0h + (size_t)cur * BH, *h0cl = g_h0l + (size_t)cur * BH;
        bf16 *h0nh = g_h0h + (size_t)nxt * BH, *h0nl = g_h0l + (size_t)nxt * BH;
        bf16 *h1ch = g_h1h + (size_t)cur * BH, *h1cl = g_h1l + (size_t)cur * BH;
        bf16 *h1nh = g_h1h + (size_t)nxt * BH, *h1nl = g_h1l + (size_t)nxt * BH;

        // Phase A: layer0 u,r h-part -> pA
        {
            int gg = bid >> 6, ks = bid & 7, nt = (bid >> 3) & 7;
            rec_mma(h0ch, h0cl, ks * 128,
                    g_wt0h + (size_t)gg * 1024 * 1024, g_wt0l + (size_t)gg * 1024 * 1024,
                    ks * 128, 1024, nt * 128, 4,
                    g_pA + (size_t)ks * 128 * 2048 + gg * 1024, 2048, sm);
        }
        grid_barrier(sense);

        // ACT A: rh0 = sig(xr + sum pA[r]) * h0c
        for (int i = bid * 256 + tid; i < BH / 2; i += RECB * 256) {
            size_t idx = (size_t)i * 2;
            int m = (int)(idx >> 10), n = (int)(idx & 1023);
            float2 s = *(const float2*)&xp[(size_t)m * XP3 + 1024 + n];
            #pragma unroll
            for (int p = 0; p < 8; ++p) {
                float2 v = __ldcg((const float2*)&g_pA[((size_t)p * 128 + m) * 2048 + 1024 + n]);
                s.x += v.x; s.y += v.y;
            }
            float2 h = __ldcg((const float2*)&h0c[idx]);
            bsplit2(g_rh0h, g_rh0l, idx, make_float2(sigf(s.x) * h.x, sigf(s.y) * h.y));
        }
        grid_barrier(sense);

        // Phase B: layer0 candidate -> pB
        {
            int ks = bid & 15, nt = bid >> 4;
            rec_mma(g_rh0h, g_rh0l, ks * 64,
                    g_wt0h + (size_t)2 * 1024 * 1024, g_wt0l + (size_t)2 * 1024 * 1024,
                    ks * 64, 1024, nt * 128, 2,
                    g_pB + (size_t)ks * 128 * 1024, 1024, sm);
        }
        grid_barrier(sense);

        // ACT B: h0n = u*h0c + (1-u)*tanh(xc + sum pB)
        for (int i = bid * 256 + tid; i < BH / 2; i += RECB * 256) {
            size_t idx = (size_t)i * 2;
            int m = (int)(idx >> 10), n = (int)(idx & 1023);
            float2 su = *(const float2*)&xp[(size_t)m * XP3 + n];
            #pragma unroll
            for (int p = 0; p < 8; ++p) {
                float2 v = __ldcg((const float2*)&g_pA[((size_t)p * 128 + m) * 2048 + n]);
                su.x += v.x; su.y += v.y;
            }
            float2 sc = *(const float2*)&xp[(size_t)m * XP3 + 2048 + n];
            #pragma unroll
            for (int p = 0; p < 16; ++p) {
                float2 v = __ldcg((const float2*)&g_pB[((size_t)p * 128 + m) * 1024 + n]);
                sc.x += v.x; sc.y += v.y;
            }
            float2 h = __ldcg((const float2*)&h0c[idx]);
            float ux = sigf(su.x), uy = sigf(su.y);
            float2 o = make_float2(ux * h.x + (1.f - ux) * tanhf(sc.x),
                                   uy * h.y + (1.f - uy) * tanhf(sc.y));
            *(float2*)&h0n[idx] = o;
            bsplit2(h0nh, h0nl, idx, o);
        }
        grid_barrier(sense);

        // Phase C: layer1 u,r over [h0n | h1c] -> pC
        {
            int gg = bid >> 6, ks = bid & 7, nt = (bid >> 3) & 7;
            int koff = ks * 256;
            const bf16* ah = (koff < 1024) ? h0nh : h1ch;
            const bf16* al = (koff < 1024) ? h0nl : h1cl;
            rec_mma(ah, al, koff & 1023,
                    g_wt1h + (size_t)gg * 1024 * 2048, g_wt1l + (size_t)gg * 1024 * 2048,
                    koff, 2048, nt * 128, 8,
                    g_pC + (size_t)ks * 128 * 2048 + gg * 1024, 2048, sm);
        }
        grid_barrier(sense);

        // ACT C: rh1 = sig(br1 + sum pC[r]) * h1c
        for (int i = bid * 256 + tid; i < BH / 2; i += RECB * 256) {
            size_t idx = (size_t)i * 2;
            int m = (int)(idx >> 10), n = (int)(idx & 1023);
            float2 s = *(const float2*)&P.br1[n];
            #pragma unroll
            for (int p = 0; p < 8; ++p) {
                float2 v = __ldcg((const float2*)&g_pC[((size_t)p * 128 + m) * 2048 + 1024 + n]);
                s.x += v.x; s.y += v.y;
            }
            float2 h = __ldcg((const float2*)&h1c[idx]);
            bsplit2(g_rh1h, g_rh1l, idx, make_float2(sigf(s.x) * h.x, sigf(s.y) * h.y));
        }
        grid_barrier(sense);

        // Phase D: layer1 candidate over [h0n | rh1] -> pD
        {
            int ks = bid & 15, nt = bid >> 4;
            int koff = ks * 128;
            const bf16* ah = (koff < 1024) ? h0nh : g_rh1h;
            const bf16* al = (koff < 1024) ? h0nl : g_rh1l;
            rec_mma(ah, al, koff & 1023,
                    g_wt1h + (size_t)2 * 1024 * 2048, g_wt1l + (size_t)2 * 1024 * 2048,
                    koff, 2048, nt * 128, 4,
                    g_pD + (size_t)ks * 128 * 1024, 1024, sm);
        }
        grid_barrier(sense);

        // ACT D: h1n; bf16 splits into logits A buffers
        {
            bf16* seqh = g_ah + (size_t)t * BH;
            bf16* seql = g_al + (size_t)t * BH;
            for (int i = bid * 256 + tid; i < BH / 2; i += RECB * 256) {
                size_t idx = (size_t)i * 2;
                int m = (int)(idx >> 10), n = (int)(idx & 1023);
                float2 su = *(const float2*)&P.bu1[n];
                #pragma unroll
                for (int p = 0; p < 8; ++p) {
                    float2 v = __ldcg((const float2*)&g_pC[((size_t)p * 128 + m) * 2048 + n]);
                    su.x += v.x; su.y += v.y;
                }
                float2 sc = *(const float2*)&P.bc1[n];
                #pragma unroll
                for (int p = 0; p < 16; ++p) {
                    float2 v = __ldcg((const float2*)&g_pD[((size_t)p * 128 + m) * 1024 + n]);
                    sc.x += v.x; sc.y += v.y;
                }
                float2 h = __ldcg((const float2*)&h1c[idx]);
                float ux = sigf(su.x), uy = sigf(su.y);
                float2 o = make_float2(ux * h.x + (1.f - ux) * tanhf(sc.x),
                                       uy * h.y + (1.f - uy) * tanhf(sc.y));
                *(float2*)&h1n[idx] = o;
                bsplit2(seqh, seql, idx, o);
                bsplit2(h1nh, h1nl, idx, o);
            }
        }
        grid_barrier(sense);

        // publish step t to logits workers (barrier above ordered the writes)
        if (bid == 0 && tid == 0) {
            __threadfence();
            g_tdone = (unsigned)(t + 1);
        }
    }

    if (bid == 0 && tid == 0) {
        __threadfence();
        g_recdone = 1u;
    }
}

// ---------------- host orchestration ----------------
extern "C" void kernel_launch(void* const* d_in, const int* in_sizes, int n_in,
                              void* d_out, int out_size)
{
    const int*   tok  = (const int*)  d_in[0];
    const float* ihs  = (const float*)d_in[1];
    const float* emb  = (const float*)d_in[2];
    const float* Wout = (const float*)d_in[3];
    const float* bout = (const float*)d_in[4];
    const float* wu0  = (const float*)d_in[5];
    const float* bu0  = (const float*)d_in[6];
    const float* wr0  = (const float*)d_in[7];
    const float* br0  = (const float*)d_in[8];
    const float* wc0  = (const float*)d_in[9];
    const float* bc0  = (const float*)d_in[10];
    const float* wu1  = (const float*)d_in[11];
    const float* bu1  = (const float*)d_in[12];
    const float* wr1  = (const float*)d_in[13];
    const float* br1  = (const float*)d_in[14];
    const float* wc1  = (const float*)d_in[15];
    const float* bc1  = (const float*)d_in[16];

    float *p_xp, *p_bias3;
    bf16 *p_ah, *p_al, *p_bth, *p_btl, *p_wt0h, *p_wt0l, *p_wt1h, *p_wt1l;
    cudaGetSymbolAddress((void**)&p_xp,    g_xp);
    cudaGetSymbolAddress((void**)&p_bias3, g_bias3);
    cudaGetSymbolAddress((void**)&p_ah,  g_ah);
    cudaGetSymbolAddress((void**)&p_al,  g_al);
    cudaGetSymbolAddress((void**)&p_bth, g_bth);
    cudaGetSymbolAddress((void**)&p_btl, g_btl);
    cudaGetSymbolAddress((void**)&p_wt0h, g_wt0h);
    cudaGetSymbolAddress((void**)&p_wt0l, g_wt0l);
    cudaGetSymbolAddress((void**)&p_wt1h, g_wt1h);
    cudaGetSymbolAddress((void**)&p_wt1l, g_wt1l);

    const int MM_SMEM = 2 * MM_STG * 2;   // 81920 B
    cudaFuncSetAttribute(mma_gemm<0>, cudaFuncAttributeMaxDynamicSharedMemorySize, MM_SMEM);
    cudaFuncSetAttribute(mma_gemm<1>, cudaFuncAttributeMaxDynamicSharedMemorySize, MM_SMEM);
    cudaFuncSetAttribute(recurrence_kernel, cudaFuncAttributeMaxDynamicSharedMemorySize, MM_SMEM);

    // 1) gather embeddings + bf16 split
    gather_kernel<<<TSEQ * BATCH, 256>>>(tok, emb);

    // 2) fused pre: one GEMM for all 3 layer-0 x-projections (N = 3072)
    dim3 tb(32, 8);
    tconv<<<dim3(32, 32), tb>>>(wu0, HID, HID, 1024, p_bth,               p_btl);
    tconv<<<dim3(32, 32), tb>>>(wr0, HID, HID, 1024, p_bth + 1024*1024,   p_btl + 1024*1024);
    tconv<<<dim3(32, 32), tb>>>(wc0, HID, HID, 1024, p_bth + 2*1024*1024, p_btl + 2*1024*1024);
    concat_bias<<<4, 256>>>(bu0, br0, bc0);
    mma_gemm<0><<<dim3(64, XP3 / 128), 256, MM_SMEM>>>(p_ah, p_al, p_bth, p_btl,
                                                        p_bias3, p_xp, XP3);

    // 3) logits weights — full transpose grid (workers consume during recurrence)
    tconv<<<dim3(NPAD / 32, 32), tb>>>(Wout, VOCAB, VOCAB, 1024, p_bth, p_btl);

    // 4) recurrence weight transposes
    const size_t EH = (size_t)EMB * HID;
    tconv<<<dim3(32, 32), tb>>>(wu0 + EH, HID, HID, 1024, p_wt0h,               p_wt0l);
    tconv<<<dim3(32, 32), tb>>>(wr0 + EH, HID, HID, 1024, p_wt0h + 1024*1024,   p_wt0l + 1024*1024);
    tconv<<<dim3(32, 32), tb>>>(wc0 + EH, HID, HID, 1024, p_wt0h + 2*1024*1024, p_wt0l + 2*1024*1024);
    tconv<<<dim3(32, 64), tb>>>(wu1, HID, HID, 2048, p_wt1h,               p_wt1l);
    tconv<<<dim3(32, 64), tb>>>(wr1, HID, HID, 2048, p_wt1h + 1024*2048,   p_wt1l + 1024*2048);
    tconv<<<dim3(32, 64), tb>>>(wc1, HID, HID, 2048, p_wt1h + 2*1024*2048, p_wt1l + 2*1024*2048);

    // 5) initial hidden state + per-launch counter reset
    init_h<<<(BH / 2 + 255) / 256, 256>>>(ihs);

    // 6) persistent kernel, 296 CTAs (2/SM): 128 recurrence + 168 logits workers
    RecParams P{bu1, br1, bc1, bout, (float*)d_out};
    recurrence_kernel<<<GRID, 256, MM_SMEM>>>(P);

    // 7) remaining logits tiles (skips j < g_ticket done in-recurrence)
    mma_gemm<1><<<dim3(64, NT80), 256, MM_SMEM>>>(p_ah, p_al, p_bth, p_btl,
                                                   bout, (float*)d_out, VOCAB);

    // 8) final states
    state_out<<<(BH + 255) / 256, 256>>>((float*)d_out, (long long)out_size);
}

// round 16
// speedup vs baseline: 1.1922x; 1.0618x over previous
#include <cuda_runtime.h>
#include <cuda_bf16.h>
#include <math.h>

#define BATCH 128
#define TSEQ  64
#define VOCAB 10000
#define EMB   1024
#define HID   1024
#define GRID  296               // 2 CTAs per SM: 128 recurrence + 168 workers
#define RECB  128
#define BH    (BATCH*HID)
#define NPAD  10240
#define NT80  (NPAD/128)        // 80 logits n-tiles
#define NJOBS (TSEQ*NT80)       // 5120 logits tiles
#define XP3   3072
#define NTPRE (XP3/128)         // 24 pre n-tiles
#define NPRE  (TSEQ*NTPRE)      // 1536 pre tiles
#define NALL  (NPRE+NJOBS)      // 6656 worker jobs

typedef unsigned long long ull;
typedef __nv_bfloat16 bf16;

__device__ __forceinline__ float sigf(float x) { return 1.f / (1.f + expf(-x)); }

// ---------------- mma.sync helpers ----------------
__device__ __forceinline__ unsigned smem_u32(const void* p) {
    unsigned a;
    asm("{ .reg .u64 t; cvta.to.shared.u64 t, %1; cvt.u32.u64 %0, t; }" : "=r"(a) : "l"(p));
    return a;
}
__device__ __forceinline__ void ldsm4(unsigned* r, unsigned a) {
    asm volatile("ldmatrix.sync.aligned.m8n8.x4.shared.b16 {%0,%1,%2,%3}, [%4];"
                 : "=r"(r[0]), "=r"(r[1]), "=r"(r[2]), "=r"(r[3]) : "r"(a));
}
__device__ __forceinline__ void mma16816(float* c, const unsigned* a, unsigned b0, unsigned b1) {
    asm volatile("mma.sync.aligned.m16n8k16.row.col.f32.bf16.bf16.f32 "
                 "{%0,%1,%2,%3}, {%4,%5,%6,%7}, {%8,%9}, {%0,%1,%2,%3};"
                 : "+f"(c[0]), "+f"(c[1]), "+f"(c[2]), "+f"(c[3])
                 : "r"(a[0]), "r"(a[1]), "r"(a[2]), "r"(a[3]), "r"(b0), "r"(b1));
}
__device__ __forceinline__ void cpa16(unsigned saddr, const void* g) {
    asm volatile("cp.async.ca.shared.global [%0], [%1], 16;" :: "r"(saddr), "l"(g));
}
__device__ __forceinline__ void cpg16(unsigned saddr, const void* g) {
    asm volatile("cp.async.cg.shared.global [%0], [%1], 16;" :: "r"(saddr), "l"(g));
}

// ---------------- device scratch ----------------
__device__ float g_xp[TSEQ*BATCH*XP3];
__device__ float g_h0buf[2*BH];
__device__ float g_h1buf[2*BH];
__device__ float g_pA[8*128*2048];
__device__ float g_pB[16*128*1024];
__device__ float g_pC[8*128*2048];
__device__ float g_pD[16*128*1024];
__device__ float g_bias3[XP3];
__device__ bf16 g_ah[TSEQ*BH];           // emb splits, then h1seq splits
__device__ bf16 g_al[TSEQ*BH];
__device__ bf16 g_bth[NPAD*1024];        // Wout^T splits
__device__ bf16 g_btl[NPAD*1024];
__device__ bf16 g_bxh[XP3*1024];         // layer0 x-weights^T splits (u|r|c)
__device__ bf16 g_bxl[XP3*1024];
__device__ bf16 g_wt0h[3*1024*1024];
__device__ bf16 g_wt0l[3*1024*1024];
__device__ bf16 g_wt1h[3*1024*2048];
__device__ bf16 g_wt1l[3*1024*2048];
__device__ bf16 g_h0h[2*BH], g_h0l[2*BH];
__device__ bf16 g_h1h[2*BH], g_h1l[2*BH];
__device__ bf16 g_rh0h[BH], g_rh0l[BH];
__device__ bf16 g_rh1h[BH], g_rh1l[BH];
__device__ unsigned g_barcnt;
__device__ volatile unsigned g_barsense;
__device__ unsigned g_ticket;            // next worker job (pre then logits)
__device__ unsigned g_pdone[TSEQ];       // completed pre tiles per step
__device__ volatile unsigned g_tdone;    // steps with h1 published
__device__ volatile unsigned g_recdone;  // recurrence finished flag

__device__ __forceinline__ void bsplit2(bf16* bh, bf16* bl, size_t idx, float2 v) {
    bf16 h0 = __float2bfloat16(v.x), h1 = __float2bfloat16(v.y);
    bf16 l0 = __float2bfloat16(v.x - __bfloat162float(h0));
    bf16 l1 = __float2bfloat16(v.y - __bfloat162float(h1));
    *(__nv_bfloat162*)(bh + idx) = __halves2bfloat162(h0, h1);
    *(__nv_bfloat162*)(bl + idx) = __halves2bfloat162(l0, l1);
}

// ---------------- small kernels ----------------
__global__ void gather_kernel(const int* __restrict__ tok, const float* __restrict__ emb) {
    int row = blockIdx.x;
    int t = row >> 7, b = row & 127;
    int token = tok[b * TSEQ + t];
    float4 v = ((const float4*)(emb + (size_t)token * EMB))[threadIdx.x];
    size_t idx = (size_t)row * EMB + threadIdx.x * 4;
    bsplit2(g_ah, g_al, idx,     make_float2(v.x, v.y));
    bsplit2(g_ah, g_al, idx + 2, make_float2(v.z, v.w));
}

__global__ void init_h(const float* __restrict__ ihs) {
    int gi = blockIdx.x * blockDim.x + threadIdx.x;
    if (gi == 0) {                 // per-launch reset (graph replays reuse globals)
        g_ticket = 0;
        g_tdone = 0;
        g_recdone = 0;
    }
    if (gi < TSEQ) g_pdone[gi] = 0;
    int i = gi * 2;
    if (i < BH) {
        float2 a = *(const float2*)&ihs[i];
        float2 b = *(const float2*)&ihs[BH + i];
        *(float2*)&g_h0buf[i] = a;
        *(float2*)&g_h1buf[i] = b;
        bsplit2(g_h0h, g_h0l, i, a);
        bsplit2(g_h1h, g_h1l, i, b);
    }
}

__global__ void concat_bias(const float* __restrict__ bu, const float* __restrict__ br,
                            const float* __restrict__ bc) {
    int i = blockIdx.x * blockDim.x + threadIdx.x;
    if (i < 1024) {
        g_bias3[i]        = bu[i];
        g_bias3[1024 + i] = br[i];
        g_bias3[2048 + i] = bc[i];
    }
}

__global__ void state_out(float* __restrict__ out, long long out_size) {
    long long i = (long long)blockIdx.x * blockDim.x + threadIdx.x;
    long long base = (long long)BATCH * TSEQ * VOCAB;
    if (i < BH) {
        if (base + i < out_size)      out[base + i]      = g_h0buf[i];
        if (base + BH + i < out_size) out[base + BH + i] = g_h1buf[i];
    }
}

__global__ void tconv(const float* __restrict__ W, int ldw, int N, int ldo,
                      bf16* __restrict__ th, bf16* __restrict__ tl) {
    __shared__ float t[32][33];
    int n0 = blockIdx.x * 32, k0 = blockIdx.y * 32;
    int tx = threadIdx.x, ty = threadIdx.y;
    #pragma unroll
    for (int r = 0; r < 4; ++r) {
        int k = k0 + ty + r * 8, n = n0 + tx;
        t[ty + r * 8][tx] = (n < N) ? W[(size_t)k * ldw + n] : 0.f;
    }
    __syncthreads();
    #pragma unroll
    for (int r = 0; r < 4; ++r) {
        int n = n0 + ty + r * 8, k = k0 + tx;
        float x = t[tx][ty + r * 8];
        bf16 hh = __float2bfloat16(x);
        th[(size_t)n * ldo + k] = hh;
        tl[(size_t)n * ldo + k] = __float2bfloat16(x - __bfloat162float(hh));
    }
}

// ---------------- shared GEMM tile body (256 thr, 8 warps, 64x32 warp tile) ----------------
#define MM_LD 40
#define MM_MS (128*MM_LD)
#define MM_STG (4*MM_MS)

template<int BCA>
__device__ __forceinline__ void tile_body(
    const bf16* Ah, const bf16* Al, size_t a_rowbase, int a_ld, int akoff,
    const bf16* Bh, const bf16* Bl, int n0, int b_ld, int bkoff,
    int kchunks, float acc[4][4][4], bf16* sm)
{
    const int tid = threadIdx.x, w = tid >> 5, l = tid & 31;
    const int mw = (w >> 2) * 64, nw = (w & 3) * 32;
    const unsigned sbase = smem_u32(sm);

    #pragma unroll
    for (int i = 0; i < 4; ++i)
        #pragma unroll
        for (int j = 0; j < 4; ++j)
            #pragma unroll
            for (int q = 0; q < 4; ++q) acc[i][j][q] = 0.f;

    auto stage_load = [&](int c, int s) {
        int kc = c * 32;
        unsigned sb = sbase + (unsigned)(s * MM_STG) * 2;
        #pragma unroll
        for (int l2 = 0; l2 < 2; ++l2) {
            int u = tid + l2 * 256;
            int row = u >> 2, q = u & 3;
            unsigned soff = (unsigned)(row * MM_LD + q * 8) * 2;
            size_t ga = a_rowbase + (size_t)row * a_ld + akoff + kc + q * 8;
            size_t gb = (size_t)(n0 + row) * b_ld + bkoff + kc + q * 8;
            cpg16(sb + 0 * MM_MS * 2 + soff, Ah + ga);
            cpg16(sb + 1 * MM_MS * 2 + soff, Al + ga);
            if (BCA) {
                cpa16(sb + 2 * MM_MS * 2 + soff, Bh + gb);
                cpa16(sb + 3 * MM_MS * 2 + soff, Bl + gb);
            } else {
                cpg16(sb + 2 * MM_MS * 2 + soff, Bh + gb);
                cpg16(sb + 3 * MM_MS * 2 + soff, Bl + gb);
            }
        }
    };

    stage_load(0, 0);
    asm volatile("cp.async.commit_group;" ::: "memory");
    const int ldrow = ((l >> 3) & 1) * 8 + (l & 7);
    const int ldcol = (l >> 4) * 8;

    for (int c = 0; c < kchunks; ++c) {
        if (c + 1 < kchunks) {
            stage_load(c + 1, (c + 1) & 1);
            asm volatile("cp.async.commit_group;" ::: "memory");
            asm volatile("cp.async.wait_group 1;" ::: "memory");
        } else {
            asm volatile("cp.async.wait_group 0;" ::: "memory");
        }
        __syncthreads();
        unsigned sb = sbase + (unsigned)((c & 1) * MM_STG) * 2;
        #pragma unroll
        for (int kk = 0; kk < 2; ++kk) {
            unsigned aH[4][4], aL[4][4], bH[4][2], bL[4][2];
            #pragma unroll
            for (int mt = 0; mt < 4; ++mt) {
                int r = mw + mt * 16 + ldrow;
                unsigned ad = sb + (unsigned)(r * MM_LD + kk * 16 + ldcol) * 2;
                ldsm4(aH[mt], ad);
                ldsm4(aL[mt], ad + MM_MS * 2);
            }
            #pragma unroll
            for (int p = 0; p < 2; ++p) {
                int r = nw + p * 16 + ldrow;
                unsigned bd = sb + (unsigned)(2 * MM_MS + r * MM_LD + kk * 16 + ldcol) * 2;
                unsigned t0[4], t1[4];
                ldsm4(t0, bd);
                ldsm4(t1, bd + MM_MS * 2);
                bH[2*p][0] = t0[0]; bH[2*p][1] = t0[2];
                bH[2*p+1][0] = t0[1]; bH[2*p+1][1] = t0[3];
                bL[2*p][0] = t1[0]; bL[2*p][1] = t1[2];
                bL[2*p+1][0] = t1[1]; bL[2*p+1][1] = t1[3];
            }
            #pragma unroll
            for (int mt = 0; mt < 4; ++mt)
                #pragma unroll
                for (int nt = 0; nt < 4; ++nt) {
                    mma16816(acc[mt][nt], aH[mt], bH[nt][0], bH[nt][1]);
                    mma16816(acc[mt][nt], aH[mt], bL[nt][0], bL[nt][1]);
                    mma16816(acc[mt][nt], aL[mt], bH[nt][0], bH[nt][1]);
                }
        }
        __syncthreads();
    }
}

// ---------------- trailing logits GEMM (ticket-offset skip) ----------------
__global__ __launch_bounds__(256, 2)
void mma_gemm_out(const bf16* __restrict__ Ah, const bf16* __restrict__ Al,
                  const bf16* __restrict__ Bh, const bf16* __restrict__ Bl,
                  const float* __restrict__ bias, float* __restrict__ C)
{
    extern __shared__ __align__(16) bf16 sm[];
    unsigned j = (unsigned)(blockIdx.x * NT80 + blockIdx.y);
    if (NPRE + j < *(volatile unsigned*)&g_ticket) return;   // done in-recurrence
    const int tid = threadIdx.x, w = tid >> 5, l = tid & 31;
    const int m0 = blockIdx.x * 128, n0 = blockIdx.y * 128;
    const int mw = (w >> 2) * 64, nw = (w & 3) * 32;

    float acc[4][4][4];
    tile_body<1>(Ah, Al, (size_t)m0 * 1024, 1024, 0, Bh, Bl, n0, 1024, 0, 32, acc, sm);

    int g = l >> 2, tg = l & 3;
    #pragma unroll
    for (int mt = 0; mt < 4; ++mt) {
        int r0 = m0 + mw + mt * 16 + g;
        int r1 = r0 + 8;
        float* crow0 = C + ((size_t)(r0 & 127) * TSEQ + (r0 >> 7)) * VOCAB;
        float* crow1 = C + ((size_t)(r1 & 127) * TSEQ + (r1 >> 7)) * VOCAB;
        #pragma unroll
        for (int nt = 0; nt < 4; ++nt) {
            int n = n0 + nw + nt * 8 + tg * 2;
            if (n < VOCAB) {
                float2 bv = *(const float2*)&bias[n];
                *(float2*)&crow0[n] = make_float2(acc[mt][nt][0] + bv.x, acc[mt][nt][1] + bv.y);
                *(float2*)&crow1[n] = make_float2(acc[mt][nt][2] + bv.x, acc[mt][nt][3] + bv.y);
            }
        }
    }
}

// ---------------- recurrence MMA tile ----------------
__device__ __noinline__ void rec_mma(
    const bf16* Ah, const bf16* Al, int akoff,
    const bf16* Bh, const bf16* Bl, int bkoff, int ldb,
    int n0, int kchunks, float* outp, int outW, bf16* sm)
{
    const int tid = threadIdx.x, w = tid >> 5, l = tid & 31;
    const int mw = (w >> 2) * 64, nw = (w & 3) * 32;
    float acc[4][4][4];
    tile_body<0>(Ah, Al, 0, 1024, akoff, Bh, Bl, n0, ldb, bkoff, kchunks, acc, sm);

    int g = l >> 2, tg = l & 3;
    #pragma unroll
    for (int mt = 0; mt < 4; ++mt) {
        int r0 = mw + mt * 16 + g;
        int r1 = r0 + 8;
        #pragma unroll
        for (int nt = 0; nt < 4; ++nt) {
            int n = n0 + nw + nt * 8 + tg * 2;
            *(float2*)&outp[(size_t)r0 * outW + n] = make_float2(acc[mt][nt][0], acc[mt][nt][1]);
            *(float2*)&outp[(size_t)r1 * outW + n] = make_float2(acc[mt][nt][2], acc[mt][nt][3]);
        }
    }
}

// ---------------- worker tiles: logits + pre ----------------
__device__ __noinline__ void logits_tile(
    int m0, int n0, const float* __restrict__ bias, float* __restrict__ C, bf16* sm)
{
    const int tid = threadIdx.x, w = tid >> 5, l = tid & 31;
    const int mw = (w >> 2) * 64, nw = (w & 3) * 32;
    float acc[4][4][4];
    tile_body<1>(g_ah, g_al, (size_t)m0 * 1024, 1024, 0, g_bth, g_btl, n0, 1024, 0, 32, acc, sm);

    int g = l >> 2, tg = l & 3;
    #pragma unroll
    for (int mt = 0; mt < 4; ++mt) {
        int r0 = m0 + mw + mt * 16 + g;
        int r1 = r0 + 8;
        float* crow0 = C + ((size_t)(r0 & 127) * TSEQ + (r0 >> 7)) * VOCAB;
        float* crow1 = C + ((size_t)(r1 & 127) * TSEQ + (r1 >> 7)) * VOCAB;
        #pragma unroll
        for (int nt = 0; nt < 4; ++nt) {
            int n = n0 + nw + nt * 8 + tg * 2;
            if (n < VOCAB) {
                float2 bv = *(const float2*)&bias[n];
                *(float2*)&crow0[n] = make_float2(acc[mt][nt][0] + bv.x, acc[mt][nt][1] + bv.y);
                *(float2*)&crow1[n] = make_float2(acc[mt][nt][2] + bv.x, acc[mt][nt][3] + bv.y);
            }
        }
    }
}

__device__ __noinline__ void pre_tile(int m0, int n0, bf16* sm)
{
    const int tid = threadIdx.x, w = tid >> 5, l = tid & 31;
    const int mw = (w >> 2) * 64, nw = (w & 3) * 32;
    float acc[4][4][4];
    tile_body<1>(g_ah, g_al, (size_t)m0 * 1024, 1024, 0, g_bxh, g_bxl, n0, 1024, 0, 32, acc, sm);

    int g = l >> 2, tg = l & 3;
    #pragma unroll
    for (int mt = 0; mt < 4; ++mt) {
        int r0 = m0 + mw + mt * 16 + g;
        int r1 = r0 + 8;
        float* crow0 = g_xp + (size_t)r0 * XP3;
        float* crow1 = g_xp + (size_t)r1 * XP3;
        #pragma unroll
        for (int nt = 0; nt < 4; ++nt) {
            int n = n0 + nw + nt * 8 + tg * 2;
            float2 bv = *(const float2*)&g_bias3[n];
            *(float2*)&crow0[n] = make_float2(acc[mt][nt][0] + bv.x, acc[mt][nt][1] + bv.y);
            *(float2*)&crow1[n] = make_float2(acc[mt][nt][2] + bv.x, acc[mt][nt][3] + bv.y);
        }
    }
}

// ---------------- persistent recurrence (+ workers), 2 CTAs/SM ----------------
struct RecParams {
    const float *bu1, *br1, *bc1;
    const float *bout;
    float *out;
};

__device__ __forceinline__ void grid_barrier(unsigned& sense) {
    __syncthreads();
    if (threadIdx.x == 0) {
        unsigned next = sense ^ 1u;
        __threadfence();
        if (atomicAdd(&g_barcnt, 1u) == RECB - 1) {
            g_barcnt = 0;
            __threadfence();
            g_barsense = next;
        } else {
            while (g_barsense != next) __nanosleep(32);
        }
    }
    sense ^= 1u;
    __syncthreads();
}

__global__ __launch_bounds__(256, 2)
void recurrence_kernel(RecParams P)
{
    extern __shared__ __align__(16) bf16 sm[];
    const int bid = blockIdx.x;
    const int tid = threadIdx.x;

    // ---- worker CTAs (168): pre tiles first (jobs 0..NPRE-1), then logits ----
    if (bid >= RECB) {
        __shared__ unsigned s_job;
        for (;;) {
            if (tid == 0) {
                unsigned j = 0xFFFFFFFFu;
                if (!g_recdone) j = atomicAdd(&g_ticket, 1u);
                s_job = j;
            }
            __syncthreads();
            unsigned j = s_job;
            __syncthreads();
            if (j >= NALL) break;                        // uniform across CTA
            if (j < NPRE) {
                int t = (int)(j / NTPRE), n0 = (int)(j % NTPRE) * 128;
                pre_tile(t * 128, n0, sm);
                __threadfence();
                __syncthreads();
                if (tid == 0) atomicAdd(&g_pdone[t], 1u);
            } else {
                unsigned jl = j - NPRE;
                int t = (int)(jl / NT80), n0 = (int)(jl % NT80) * 128;
                if (tid == 0) {
                    while (g_tdone <= (unsigned)t) __nanosleep(64);
                }
                __syncthreads();
                logits_tile(t * 128, n0, P.bout, P.out, sm);
            }
        }
        return;
    }

    // ---- recurrence CTAs (128) ----
    unsigned sense = 0;
    for (int t = 0; t < TSEQ; ++t) {
        const int cur = t & 1, nxt = cur ^ 1;
        const float* xp = g_xp + (size_t)t * BATCH * XP3;
        float* h0c = g_h0buf + (size_t)cur * BH;
        float* h0n = g_h0buf + (size_t)nxt * BH;
        float* h1c = g_h1buf + (size_t)cur * BH;
        float* h1n = g_h1buf + (size_t)nxt * BH;
        bf16 *h0ch = g_h0h + (size_t)cur * BH, *h0cl = g_h0l + (size_t)cur * BH;
        bf16 *h0nh = g_h0h + (size_t)nxt * BH, *h0nl = g_h0l + (size_t)nxt * BH;
        bf16 *h1ch = g_h1h + (size_t)cur * BH, *h1cl = g_h1l + (size_t)cur * BH;
        bf16 *h1nh = g_h1h + (size_t)nxt * BH, *h1nl = g_h1l + (size_t)nxt * BH;

        // Phase A: layer0 u,r h-part -> pA
        {
            int gg = bid >> 6, ks = bid & 7, nt = (bid >> 3) & 7;
            rec_mma(h0ch, h0cl, ks * 128,
                    g_wt0h + (size_t)gg * 1024 * 1024, g_wt0l + (size_t)gg * 1024 * 1024,
                    ks * 128, 1024, nt * 128, 4,
                    g_pA + (size_t)ks * 128 * 2048 + gg * 1024, 2048, sm);
        }
        grid_barrier(sense);

        // wait for this step's x-preacts (produced by worker pre tiles)
        if (tid == 0) {
            while (*(volatile unsigned*)&g_pdone[t] < (unsigned)NTPRE) __nanosleep(64);
        }
        __syncthreads();

        // ACT A: rh0 = sig(xr + sum pA[r]) * h0c
        for (int i = bid * 256 + tid; i < BH / 2; i += RECB * 256) {
            size_t idx = (size_t)i * 2;
            int m = (int)(idx >> 10), n = (int)(idx & 1023);
            float2 s = *(const float2*)&xp[(size_t)m * XP3 + 1024 + n];
            #pragma unroll
            for (int p = 0; p < 8; ++p) {
                float2 v = __ldcg((const float2*)&g_pA[((size_t)p * 128 + m) * 2048 + 1024 + n]);
                s.x += v.x; s.y += v.y;
            }
            float2 h = __ldcg((const float2*)&h0c[idx]);
            bsplit2(g_rh0h, g_rh0l, idx, make_float2(sigf(s.x) * h.x, sigf(s.y) * h.y));
        }
        grid_barrier(sense);

        // Phase B: layer0 candidate -> pB
        {
            int ks = bid & 15, nt = bid >> 4;
            rec_mma(g_rh0h, g_rh0l, ks * 64,
                    g_wt0h + (size_t)2 * 1024 * 1024, g_wt0l + (size_t)2 * 1024 * 1024,
                    ks * 64, 1024, nt * 128, 2,
                    g_pB + (size_t)ks * 128 * 1024, 1024, sm);
        }
        grid_barrier(sense);

        // ACT B: h0n = u*h0c + (1-u)*tanh(xc + sum pB)
        for (int i = bid * 256 + tid; i < BH / 2; i += RECB * 256) {
            size_t idx = (size_t)i * 2;
            int m = (int)(idx >> 10), n = (int)(idx & 1023);
            float2 su = *(const float2*)&xp[(size_t)m * XP3 + n];
            #pragma unroll
            for (int p = 0; p < 8; ++p) {
                float2 v = __ldcg((const float2*)&g_pA[((size_t)p * 128 + m) * 2048 + n]);
                su.x += v.x; su.y += v.y;
            }
            float2 sc = *(const float2*)&xp[(size_t)m * XP3 + 2048 + n];
            #pragma unroll
            for (int p = 0; p < 16; ++p) {
                float2 v = __ldcg((const float2*)&g_pB[((size_t)p * 128 + m) * 1024 + n]);
                sc.x += v.x; sc.y += v.y;
            }
            float2 h = __ldcg((const float2*)&h0c[idx]);
            float ux = sigf(su.x), uy = sigf(su.y);
            float2 o = make_float2(ux * h.x + (1.f - ux) * tanhf(sc.x),
                                   uy * h.y + (1.f - uy) * tanhf(sc.y));
            *(float2*)&h0n[idx] = o;
            bsplit2(h0nh, h0nl, idx, o);
        }
        grid_barrier(sense);

        // Phase C: layer1 u,r over [h0n | h1c] -> pC
        {
            int gg = bid >> 6, ks = bid & 7, nt = (bid >> 3) & 7;
            int koff = ks * 256;
            const bf16* ah = (koff < 1024) ? h0nh : h1ch;
            const bf16* al = (koff < 1024) ? h0nl : h1cl;
            rec_mma(ah, al, koff & 1023,
                    g_wt1h + (size_t)gg * 1024 * 2048, g_wt1l + (size_t)gg * 1024 * 2048,
                    koff, 2048, nt * 128, 8,
                    g_pC + (size_t)ks * 128 * 2048 + gg * 1024, 2048, sm);
        }
        grid_barrier(sense);

        // ACT C: rh1 = sig(br1 + sum pC[r]) * h1c
        for (int i = bid * 256 + tid; i < BH / 2; i += RECB * 256) {
            size_t idx = (size_t)i * 2;
            int m = (int)(idx >> 10), n = (int)(idx & 1023);
            float2 s = *(const float2*)&P.br1[n];
            #pragma unroll
            for (int p = 0; p < 8; ++p) {
                float2 v = __ldcg((const float2*)&g_pC[((size_t)p * 128 + m) * 2048 + 1024 + n]);
                s.x += v.x; s.y += v.y;
            }
            float2 h = __ldcg((const float2*)&h1c[idx]);
            bsplit2(g_rh1h, g_rh1l, idx, make_float2(sigf(s.x) * h.x, sigf(s.y) * h.y));
        }
        grid_barrier(sense);

        // Phase D: layer1 candidate over [h0n | rh1] -> pD
        {
            int ks = bid & 15, nt = bid >> 4;
            int koff = ks * 128;
            const bf16* ah = (koff < 1024) ? h0nh : g_rh1h;
            const bf16* al = (koff < 1024) ? h0nl : g_rh1l;
            rec_mma(ah, al, koff & 1023,
                    g_wt1h + (size_t)2 * 1024 * 2048, g_wt1l + (size_t)2 * 1024 * 2048,
                    koff, 2048, nt * 128, 4,
                    g_pD + (size_t)ks * 128 * 1024, 1024, sm);
        }
        grid_barrier(sense);

        // ACT D: h1n; bf16 splits into logits A buffers
        {
            bf16* seqh = g_ah + (size_t)t * BH;
            bf16* seql = g_al + (size_t)t * BH;
            for (int i = bid * 256 + tid; i < BH / 2; i += RECB * 256) {
                size_t idx = (size_t)i * 2;
                int m = (int)(idx >> 10), n = (int)(idx & 1023);
                float2 su = *(const float2*)&P.bu1[n];
                #pragma unroll
                for (int p = 0; p < 8; ++p) {
                    float2 v = __ldcg((const float2*)&g_pC[((size_t)p * 128 + m) * 2048 + n]);
                    su.x += v.x; su.y += v.y;
                }
                float2 sc = *(const float2*)&P.bc1[n];
                #pragma unroll
                for (int p = 0; p < 16; ++p) {
                    float2 v = __ldcg((const float2*)&g_pD[((size_t)p * 128 + m) * 1024 + n]);
                    sc.x += v.x; sc.y += v.y;
                }
                float2 h = __ldcg((const float2*)&h1c[idx]);
                float ux = sigf(su.x), uy = sigf(su.y);
                float2 o = make_float2(ux * h.x + (1.f - ux) * tanhf(sc.x),
                                       uy * h.y + (1.f - uy) * tanhf(sc.y));
                *(float2*)&h1n[idx] = o;
                bsplit2(seqh, seql, idx, o);
                bsplit2(h1nh, h1nl, idx, o);
            }
        }
        grid_barrier(sense);

        // publish step t to logits workers (barrier above ordered the writes)
        if (bid == 0 && tid == 0) {
            __threadfence();
            g_tdone = (unsigned)(t + 1);
        }
    }

    if (bid == 0 && tid == 0) {
        __threadfence();
        g_recdone = 1u;
    }
}

// ---------------- host orchestration ----------------
extern "C" void kernel_launch(void* const* d_in, const int* in_sizes, int n_in,
                              void* d_out, int out_size)
{
    const int*   tok  = (const int*)  d_in[0];
    const float* ihs  = (const float*)d_in[1];
    const float* emb  = (const float*)d_in[2];
    const float* Wout = (const float*)d_in[3];
    const float* bout = (const float*)d_in[4];
    const float* wu0  = (const float*)d_in[5];
    const float* bu0  = (const float*)d_in[6];
    const float* wr0  = (const float*)d_in[7];
    const float* br0  = (const float*)d_in[8];
    const float* wc0  = (const float*)d_in[9];
    const float* bc0  = (const float*)d_in[10];
    const float* wu1  = (const float*)d_in[11];
    const float* bu1  = (const float*)d_in[12];
    const float* wr1  = (const float*)d_in[13];
    const float* br1  = (const float*)d_in[14];
    const float* wc1  = (const float*)d_in[15];
    const float* bc1  = (const float*)d_in[16];

    bf16 *p_ah, *p_al, *p_bth, *p_btl, *p_bxh, *p_bxl;
    bf16 *p_wt0h, *p_wt0l, *p_wt1h, *p_wt1l;
    cudaGetSymbolAddress((void**)&p_ah,  g_ah);
    cudaGetSymbolAddress((void**)&p_al,  g_al);
    cudaGetSymbolAddress((void**)&p_bth, g_bth);
    cudaGetSymbolAddress((void**)&p_btl, g_btl);
    cudaGetSymbolAddress((void**)&p_bxh, g_bxh);
    cudaGetSymbolAddress((void**)&p_bxl, g_bxl);
    cudaGetSymbolAddress((void**)&p_wt0h, g_wt0h);
    cudaGetSymbolAddress((void**)&p_wt0l, g_wt0l);
    cudaGetSymbolAddress((void**)&p_wt1h, g_wt1h);
    cudaGetSymbolAddress((void**)&p_wt1l, g_wt1l);

    const int MM_SMEM = 2 * MM_STG * 2;   // 81920 B
    cudaFuncSetAttribute(mma_gemm_out, cudaFuncAttributeMaxDynamicSharedMemorySize, MM_SMEM);
    cudaFuncSetAttribute(recurrence_kernel, cudaFuncAttributeMaxDynamicSharedMemorySize, MM_SMEM);

    // 1) gather embeddings + bf16 split
    gather_kernel<<<TSEQ * BATCH, 256>>>(tok, emb);

    // 2) weight transposes: layer0 x-weights (for worker pre tiles), Wout, recurrence
    dim3 tb(32, 8);
    tconv<<<dim3(32, 32), tb>>>(wu0, HID, HID, 1024, p_bxh,               p_bxl);
    tconv<<<dim3(32, 32), tb>>>(wr0, HID, HID, 1024, p_bxh + 1024*1024,   p_bxl + 1024*1024);
    tconv<<<dim3(32, 32), tb>>>(wc0, HID, HID, 1024, p_bxh + 2*1024*1024, p_bxl + 2*1024*1024);
    concat_bias<<<4, 256>>>(bu0, br0, bc0);
    tconv<<<dim3(NPAD / 32, 32), tb>>>(Wout, VOCAB, VOCAB, 1024, p_bth, p_btl);
    const size_t EH = (size_t)EMB * HID;
    tconv<<<dim3(32, 32), tb>>>(wu0 + EH, HID, HID, 1024, p_wt0h,               p_wt0l);
    tconv<<<dim3(32, 32), tb>>>(wr0 + EH, HID, HID, 1024, p_wt0h + 1024*1024,   p_wt0l + 1024*1024);
    tconv<<<dim3(32, 32), tb>>>(wc0 + EH, HID, HID, 1024, p_wt0h + 2*1024*1024, p_wt0l + 2*1024*1024);
    tconv<<<dim3(32, 64), tb>>>(wu1, HID, HID, 2048, p_wt1h,               p_wt1l);
    tconv<<<dim3(32, 64), tb>>>(wr1, HID, HID, 2048, p_wt1h + 1024*2048,   p_wt1l + 1024*2048);
    tconv<<<dim3(32, 64), tb>>>(wc1, HID, HID, 2048, p_wt1h + 2*1024*2048, p_wt1l + 2*1024*2048);

    // 3) initial hidden state + per-launch counter reset
    init_h<<<(BH / 2 + 255) / 256, 256>>>(ihs);

    // 4) persistent kernel, 296 CTAs (2/SM): 128 recurrence + 168 workers
    //    workers do 1536 pre tiles first, then 5120 logits tiles
    RecParams P{bu1, br1, bc1, bout, (float*)d_out};
    recurrence_kernel<<<GRID, 256, MM_SMEM>>>(P);

    // 5) remaining logits tiles (skips jobs claimed in-recurrence)
    mma_gemm_out<<<dim3(64, NT80), 256, MM_SMEM>>>(p_ah, p_al, p_bth, p_btl,
                                                    bout, (float*)d_out);

    // 6) final states
    state_out<<<(BH + 255) / 256, 256>>>((float*)d_out, (long long)out_size);
}

// round 17
// speedup vs baseline: 1.1927x; 1.0005x over previous
#include <cuda_runtime.h>
#include <cuda_bf16.h>
#include <math.h>

#define BATCH 128
#define TSEQ  64
#define VOCAB 10000
#define EMB   1024
#define HID   1024
#define GRID  296               // 2 CTAs per SM: 128 recurrence + 168 workers
#define RECB  128
#define BH    (BATCH*HID)
#define NPAD  10240
#define NTL   79                // logits n-tiles (80th tile is fully >= VOCAB)
#define NJOBS (TSEQ*NTL)        // 5056 logits tiles
#define XP3   3072
#define NTPRE (XP3/128)         // 24 pre n-tiles
#define NPRE  (TSEQ*NTPRE)      // 1536 pre tiles
#define NALL  (NPRE+NJOBS)      // worker jobs

typedef unsigned long long ull;
typedef __nv_bfloat16 bf16;

__device__ __forceinline__ float sigf(float x) { return 1.f / (1.f + expf(-x)); }

// ---------------- mma.sync helpers ----------------
__device__ __forceinline__ unsigned smem_u32(const void* p) {
    unsigned a;
    asm("{ .reg .u64 t; cvta.to.shared.u64 t, %1; cvt.u32.u64 %0, t; }" : "=r"(a) : "l"(p));
    return a;
}
__device__ __forceinline__ void ldsm4(unsigned* r, unsigned a) {
    asm volatile("ldmatrix.sync.aligned.m8n8.x4.shared.b16 {%0,%1,%2,%3}, [%4];"
                 : "=r"(r[0]), "=r"(r[1]), "=r"(r[2]), "=r"(r[3]) : "r"(a));
}
__device__ __forceinline__ void mma16816(float* c, const unsigned* a, unsigned b0, unsigned b1) {
    asm volatile("mma.sync.aligned.m16n8k16.row.col.f32.bf16.bf16.f32 "
                 "{%0,%1,%2,%3}, {%4,%5,%6,%7}, {%8,%9}, {%0,%1,%2,%3};"
                 : "+f"(c[0]), "+f"(c[1]), "+f"(c[2]), "+f"(c[3])
                 : "r"(a[0]), "r"(a[1]), "r"(a[2]), "r"(a[3]), "r"(b0), "r"(b1));
}
__device__ __forceinline__ void cpa16(unsigned saddr, const void* g) {
    asm volatile("cp.async.ca.shared.global [%0], [%1], 16;" :: "r"(saddr), "l"(g));
}
__device__ __forceinline__ void cpg16(unsigned saddr, const void* g) {
    asm volatile("cp.async.cg.shared.global [%0], [%1], 16;" :: "r"(saddr), "l"(g));
}

// ---------------- device scratch ----------------
__device__ float g_xp[TSEQ*BATCH*XP3];
__device__ float g_h0buf[2*BH];
__device__ float g_h1buf[2*BH];
__device__ float g_pA[8*128*2048];
__device__ float g_pB[16*128*1024];
__device__ float g_pC[8*128*2048];
__device__ float g_pD[16*128*1024];
__device__ float g_bias3[XP3];
__device__ bf16 g_ah[TSEQ*BH];           // emb splits, then h1seq splits
__device__ bf16 g_al[TSEQ*BH];
__device__ bf16 g_bth[NPAD*1024];        // Wout^T splits
__device__ bf16 g_btl[NPAD*1024];
__device__ bf16 g_bxh[XP3*1024];         // layer0 x-weights^T splits (u|r|c)
__device__ bf16 g_bxl[XP3*1024];
__device__ bf16 g_wt0h[3*1024*1024];
__device__ bf16 g_wt0l[3*1024*1024];
__device__ bf16 g_wt1h[3*1024*2048];
__device__ bf16 g_wt1l[3*1024*2048];
__device__ bf16 g_h0h[2*BH], g_h0l[2*BH];
__device__ bf16 g_h1h[2*BH], g_h1l[2*BH];
__device__ bf16 g_rh0h[BH], g_rh0l[BH];
__device__ bf16 g_rh1h[BH], g_rh1l[BH];
__device__ unsigned g_barcnt;
__device__ volatile unsigned g_barsense;
__device__ unsigned g_ticket;            // next worker job (pre then logits)
__device__ unsigned g_pdone[TSEQ];       // completed pre tiles per step
__device__ volatile unsigned g_tdone;    // steps with h1 published
__device__ volatile unsigned g_recdone;  // recurrence finished flag

__device__ __forceinline__ void bsplit2(bf16* bh, bf16* bl, size_t idx, float2 v) {
    bf16 h0 = __float2bfloat16(v.x), h1 = __float2bfloat16(v.y);
    bf16 l0 = __float2bfloat16(v.x - __bfloat162float(h0));
    bf16 l1 = __float2bfloat16(v.y - __bfloat162float(h1));
    *(__nv_bfloat162*)(bh + idx) = __halves2bfloat162(h0, h1);
    *(__nv_bfloat162*)(bl + idx) = __halves2bfloat162(l0, l1);
}

// ---------------- small kernels ----------------
__global__ void gather_kernel(const int* __restrict__ tok, const float* __restrict__ emb) {
    int row = blockIdx.x;
    int t = row >> 7, b = row & 127;
    int token = tok[b * TSEQ + t];
    float4 v = ((const float4*)(emb + (size_t)token * EMB))[threadIdx.x];
    size_t idx = (size_t)row * EMB + threadIdx.x * 4;
    bsplit2(g_ah, g_al, idx,     make_float2(v.x, v.y));
    bsplit2(g_ah, g_al, idx + 2, make_float2(v.z, v.w));
}

__global__ void init_h(const float* __restrict__ ihs,
                       const float* __restrict__ bu, const float* __restrict__ br,
                       const float* __restrict__ bc) {
    int gi = blockIdx.x * blockDim.x + threadIdx.x;
    if (gi == 0) {                 // per-launch reset (graph replays reuse globals)
        g_ticket = 0;
        g_tdone = 0;
        g_recdone = 0;
    }
    if (gi < TSEQ) g_pdone[gi] = 0;
    if (gi < 1024) {
        g_bias3[gi]        = bu[gi];
        g_bias3[1024 + gi] = br[gi];
        g_bias3[2048 + gi] = bc[gi];
    }
    int i = gi * 2;
    if (i < BH) {
        float2 a = *(const float2*)&ihs[i];
        float2 b = *(const float2*)&ihs[BH + i];
        *(float2*)&g_h0buf[i] = a;
        *(float2*)&g_h1buf[i] = b;
        bsplit2(g_h0h, g_h0l, i, a);
        bsplit2(g_h1h, g_h1l, i, b);
    }
}

__global__ void state_out(float* __restrict__ out, long long out_size) {
    long long i = (long long)blockIdx.x * blockDim.x + threadIdx.x;
    long long base = (long long)BATCH * TSEQ * VOCAB;
    if (i < BH) {
        if (base + i < out_size)      out[base + i]      = g_h0buf[i];
        if (base + BH + i < out_size) out[base + BH + i] = g_h1buf[i];
    }
}

// ---------------- batched transpose+split: all 10 weight jobs in ONE launch ----------------
struct TJob {
    const float* W; int ldw, N, ldo;
    bf16 *th, *tl;
    int nbx, nby, base;            // grid tiling + cumulative block base
};
struct TJobs { TJob j[10]; int total; };

__global__ void tconv_all(TJobs P) {
    __shared__ float t[32][33];
    int b = blockIdx.x;
    int ji = 0;
    #pragma unroll
    for (int q = 0; q < 10; ++q)
        if (b >= P.j[q].base) ji = q;
    const TJob& J = P.j[ji];
    int r = b - J.base;
    int n0 = (r % J.nbx) * 32, k0 = (r / J.nbx) * 32;
    int tx = threadIdx.x, ty = threadIdx.y;
    #pragma unroll
    for (int rr = 0; rr < 4; ++rr) {
        int k = k0 + ty + rr * 8, n = n0 + tx;
        t[ty + rr * 8][tx] = (n < J.N) ? J.W[(size_t)k * J.ldw + n] : 0.f;
    }
    __syncthreads();
    #pragma unroll
    for (int rr = 0; rr < 4; ++rr) {
        int n = n0 + ty + rr * 8, k = k0 + tx;
        float x = t[tx][ty + rr * 8];
        bf16 hh = __float2bfloat16(x);
        J.th[(size_t)n * J.ldo + k] = hh;
        J.tl[(size_t)n * J.ldo + k] = __float2bfloat16(x - __bfloat162float(hh));
    }
}

// ---------------- shared GEMM tile body (256 thr, 8 warps, 64x32 warp tile) ----------------
#define MM_LD 40
#define MM_MS (128*MM_LD)
#define MM_STG (4*MM_MS)

template<int BCA>
__device__ __forceinline__ void tile_body(
    const bf16* Ah, const bf16* Al, size_t a_rowbase, int a_ld, int akoff,
    const bf16* Bh, const bf16* Bl, int n0, int b_ld, int bkoff,
    int kchunks, float acc[4][4][4], bf16* sm)
{
    const int tid = threadIdx.x, w = tid >> 5, l = tid & 31;
    const int mw = (w >> 2) * 64, nw = (w & 3) * 32;
    const unsigned sbase = smem_u32(sm);

    #pragma unroll
    for (int i = 0; i < 4; ++i)
        #pragma unroll
        for (int j = 0; j < 4; ++j)
            #pragma unroll
            for (int q = 0; q < 4; ++q) acc[i][j][q] = 0.f;

    auto stage_load = [&](int c, int s) {
        int kc = c * 32;
        unsigned sb = sbase + (unsigned)(s * MM_STG) * 2;
        #pragma unroll
        for (int l2 = 0; l2 < 2; ++l2) {
            int u = tid + l2 * 256;
            int row = u >> 2, q = u & 3;
            unsigned soff = (unsigned)(row * MM_LD + q * 8) * 2;
            size_t ga = a_rowbase + (size_t)row * a_ld + akoff + kc + q * 8;
            size_t gb = (size_t)(n0 + row) * b_ld + bkoff + kc + q * 8;
            cpg16(sb + 0 * MM_MS * 2 + soff, Ah + ga);
            cpg16(sb + 1 * MM_MS * 2 + soff, Al + ga);
            if (BCA) {
                cpa16(sb + 2 * MM_MS * 2 + soff, Bh + gb);
                cpa16(sb + 3 * MM_MS * 2 + soff, Bl + gb);
            } else {
                cpg16(sb + 2 * MM_MS * 2 + soff, Bh + gb);
                cpg16(sb + 3 * MM_MS * 2 + soff, Bl + gb);
            }
        }
    };

    stage_load(0, 0);
    asm volatile("cp.async.commit_group;" ::: "memory");
    const int ldrow = ((l >> 3) & 1) * 8 + (l & 7);
    const int ldcol = (l >> 4) * 8;

    for (int c = 0; c < kchunks; ++c) {
        if (c + 1 < kchunks) {
            stage_load(c + 1, (c + 1) & 1);
            asm volatile("cp.async.commit_group;" ::: "memory");
            asm volatile("cp.async.wait_group 1;" ::: "memory");
        } else {
            asm volatile("cp.async.wait_group 0;" ::: "memory");
        }
        __syncthreads();
        unsigned sb = sbase + (unsigned)((c & 1) * MM_STG) * 2;
        #pragma unroll
        for (int kk = 0; kk < 2; ++kk) {
            unsigned aH[4][4], aL[4][4], bH[4][2], bL[4][2];
            #pragma unroll
            for (int mt = 0; mt < 4; ++mt) {
                int r = mw + mt * 16 + ldrow;
                unsigned ad = sb + (unsigned)(r * MM_LD + kk * 16 + ldcol) * 2;
                ldsm4(aH[mt], ad);
                ldsm4(aL[mt], ad + MM_MS * 2);
            }
            #pragma unroll
            for (int p = 0; p < 2; ++p) {
                int r = nw + p * 16 + ldrow;
                unsigned bd = sb + (unsigned)(2 * MM_MS + r * MM_LD + kk * 16 + ldcol) * 2;
                unsigned t0[4], t1[4];
                ldsm4(t0, bd);
                ldsm4(t1, bd + MM_MS * 2);
                bH[2*p][0] = t0[0]; bH[2*p][1] = t0[2];
                bH[2*p+1][0] = t0[1]; bH[2*p+1][1] = t0[3];
                bL[2*p][0] = t1[0]; bL[2*p][1] = t1[2];
                bL[2*p+1][0] = t1[1]; bL[2*p+1][1] = t1[3];
            }
            #pragma unroll
            for (int mt = 0; mt < 4; ++mt)
                #pragma unroll
                for (int nt = 0; nt < 4; ++nt) {
                    mma16816(acc[mt][nt], aH[mt], bH[nt][0], bH[nt][1]);
                    mma16816(acc[mt][nt], aH[mt], bL[nt][0], bL[nt][1]);
                    mma16816(acc[mt][nt], aL[mt], bH[nt][0], bH[nt][1]);
                }
        }
        __syncthreads();
    }
}

// ---------------- trailing logits GEMM (ticket-offset skip) ----------------
__global__ __launch_bounds__(256, 2)
void mma_gemm_out(const bf16* __restrict__ Ah, const bf16* __restrict__ Al,
                  const bf16* __restrict__ Bh, const bf16* __restrict__ Bl,
                  const float* __restrict__ bias, float* __restrict__ C)
{
    extern __shared__ __align__(16) bf16 sm[];
    unsigned j = (unsigned)(blockIdx.x * NTL + blockIdx.y);
    if (NPRE + j < *(volatile unsigned*)&g_ticket) return;   // done in-recurrence
    const int tid = threadIdx.x, w = tid >> 5, l = tid & 31;
    const int m0 = blockIdx.x * 128, n0 = blockIdx.y * 128;
    const int mw = (w >> 2) * 64, nw = (w & 3) * 32;

    float acc[4][4][4];
    tile_body<1>(Ah, Al, (size_t)m0 * 1024, 1024, 0, Bh, Bl, n0, 1024, 0, 32, acc, sm);

    int g = l >> 2, tg = l & 3;
    #pragma unroll
    for (int mt = 0; mt < 4; ++mt) {
        int r0 = m0 + mw + mt * 16 + g;
        int r1 = r0 + 8;
        float* crow0 = C + ((size_t)(r0 & 127) * TSEQ + (r0 >> 7)) * VOCAB;
        float* crow1 = C + ((size_t)(r1 & 127) * TSEQ + (r1 >> 7)) * VOCAB;
        #pragma unroll
        for (int nt = 0; nt < 4; ++nt) {
            int n = n0 + nw + nt * 8 + tg * 2;
            if (n < VOCAB) {
                float2 bv = *(const float2*)&bias[n];
                *(float2*)&crow0[n] = make_float2(acc[mt][nt][0] + bv.x, acc[mt][nt][1] + bv.y);
                *(float2*)&crow1[n] = make_float2(acc[mt][nt][2] + bv.x, acc[mt][nt][3] + bv.y);
            }
        }
    }
}

// ---------------- recurrence MMA tile ----------------
__device__ __noinline__ void rec_mma(
    const bf16* Ah, const bf16* Al, int akoff,
    const bf16* Bh, const bf16* Bl, int bkoff, int ldb,
    int n0, int kchunks, float* outp, int outW, bf16* sm)
{
    const int tid = threadIdx.x, w = tid >> 5, l = tid & 31;
    const int mw = (w >> 2) * 64, nw = (w & 3) * 32;
    float acc[4][4][4];
    tile_body<0>(Ah, Al, 0, 1024, akoff, Bh, Bl, n0, ldb, bkoff, kchunks, acc, sm);

    int g = l >> 2, tg = l & 3;
    #pragma unroll
    for (int mt = 0; mt < 4; ++mt) {
        int r0 = mw + mt * 16 + g;
        int r1 = r0 + 8;
        #pragma unroll
        for (int nt = 0; nt < 4; ++nt) {
            int n = n0 + nw + nt * 8 + tg * 2;
            *(float2*)&outp[(size_t)r0 * outW + n] = make_float2(acc[mt][nt][0], acc[mt][nt][1]);
            *(float2*)&outp[(size_t)r1 * outW + n] = make_float2(acc[mt][nt][2], acc[mt][nt][3]);
        }
    }
}

// ---------------- worker tiles: logits + pre ----------------
__device__ __noinline__ void logits_tile(
    int m0, int n0, const float* __restrict__ bias, float* __restrict__ C, bf16* sm)
{
    const int tid = threadIdx.x, w = tid >> 5, l = tid & 31;
    const int mw = (w >> 2) * 64, nw = (w & 3) * 32;
    float acc[4][4][4];
    tile_body<1>(g_ah, g_al, (size_t)m0 * 1024, 1024, 0, g_bth, g_btl, n0, 1024, 0, 32, acc, sm);

    int g = l >> 2, tg = l & 3;
    #pragma unroll
    for (int mt = 0; mt < 4; ++mt) {
        int r0 = m0 + mw + mt * 16 + g;
        int r1 = r0 + 8;
        float* crow0 = C + ((size_t)(r0 & 127) * TSEQ + (r0 >> 7)) * VOCAB;
        float* crow1 = C + ((size_t)(r1 & 127) * TSEQ + (r1 >> 7)) * VOCAB;
        #pragma unroll
        for (int nt = 0; nt < 4; ++nt) {
            int n = n0 + nw + nt * 8 + tg * 2;
            if (n < VOCAB) {
                float2 bv = *(const float2*)&bias[n];
                *(float2*)&crow0[n] = make_float2(acc[mt][nt][0] + bv.x, acc[mt][nt][1] + bv.y);
                *(float2*)&crow1[n] = make_float2(acc[mt][nt][2] + bv.x, acc[mt][nt][3] + bv.y);
            }
        }
    }
}

__device__ __noinline__ void pre_tile(int m0, int n0, bf16* sm)
{
    const int tid = threadIdx.x, w = tid >> 5, l = tid & 31;
    const int mw = (w >> 2) * 64, nw = (w & 3) * 32;
    float acc[4][4][4];
    tile_body<1>(g_ah, g_al, (size_t)m0 * 1024, 1024, 0, g_bxh, g_bxl, n0, 1024, 0, 32, acc, sm);

    int g = l >> 2, tg = l & 3;
    #pragma unroll
    for (int mt = 0; mt < 4; ++mt) {
        int r0 = m0 + mw + mt * 16 + g;
        int r1 = r0 + 8;
        float* crow0 = g_xp + (size_t)r0 * XP3;
        float* crow1 = g_xp + (size_t)r1 * XP3;
        #pragma unroll
        for (int nt = 0; nt < 4; ++nt) {
            int n = n0 + nw + nt * 8 + tg * 2;
            float2 bv = *(const float2*)&g_bias3[n];
            *(float2*)&crow0[n] = make_float2(acc[mt][nt][0] + bv.x, acc[mt][nt][1] + bv.y);
            *(float2*)&crow1[n] = make_float2(acc[mt][nt][2] + bv.x, acc[mt][nt][3] + bv.y);
        }
    }
}

// ---------------- persistent recurrence (+ workers), 2 CTAs/SM ----------------
struct RecParams {
    const float *bu1, *br1, *bc1;
    const float *bout;
    float *out;
};

__device__ __forceinline__ void grid_barrier(unsigned& sense) {
    __syncthreads();
    if (threadIdx.x == 0) {
        unsigned next = sense ^ 1u;
        __threadfence();
        if (atomicAdd(&g_barcnt, 1u) == RECB - 1) {
            g_barcnt = 0;
            __threadfence();
            g_barsense = next;
        } else {
            while (g_barsense != next) __nanosleep(16);
        }
    }
    sense ^= 1u;
    __syncthreads();
}

__global__ __launch_bounds__(256, 2)
void recurrence_kernel(RecParams P)
{
    extern __shared__ __align__(16) bf16 sm[];
    const int bid = blockIdx.x;
    const int tid = threadIdx.x;

    // ---- worker CTAs (168): pre tiles first (jobs 0..NPRE-1), then logits ----
    if (bid >= RECB) {
        __shared__ unsigned s_job;
        for (;;) {
            if (tid == 0) {
                unsigned j = 0xFFFFFFFFu;
                if (!g_recdone) j = atomicAdd(&g_ticket, 1u);
                s_job = j;
            }
            __syncthreads();
            unsigned j = s_job;
            __syncthreads();
            if (j >= NALL) break;                        // uniform across CTA
            if (j < NPRE) {
                int t = (int)(j / NTPRE), n0 = (int)(j % NTPRE) * 128;
                pre_tile(t * 128, n0, sm);
                __threadfence();
                __syncthreads();
                if (tid == 0) atomicAdd(&g_pdone[t], 1u);
            } else {
                unsigned jl = j - NPRE;
                int t = (int)(jl / NTL), n0 = (int)(jl % NTL) * 128;
                if (tid == 0) {
                    while (g_tdone <= (unsigned)t) __nanosleep(32);
                }
                __syncthreads();
                logits_tile(t * 128, n0, P.bout, P.out, sm);
            }
        }
        return;
    }

    // ---- recurrence CTAs (128) ----
    unsigned sense = 0;
    for (int t = 0; t < TSEQ; ++t) {
        const int cur = t & 1, nxt = cur ^ 1;
        const float* xp = g_xp + (size_t)t * BATCH * XP3;
        float* h0c = g_h0buf + (size_t)cur * BH;
        float* h0n = g_h0buf + (size_t)nxt * BH;
        float* h1c = g_h1buf + (size_t)cur * BH;
        float* h1n = g_h1buf + (size_t)nxt * BH;
        bf16 *h0ch = g_h0h + (size_t)cur * BH, *h0cl = g_h0l + (size_t)cur * BH;
        bf16 *h0nh = g_h0h + (size_t)nxt * BH, *h0nl = g_h0l + (size_t)nxt * BH;
        bf16 *h1ch = g_h1h + (size_t)cur * BH, *h1cl = g_h1l + (size_t)cur * BH;
        bf16 *h1nh = g_h1h + (size_t)nxt * BH, *h1nl = g_h1l + (size_t)nxt * BH;

        // Phase A: layer0 u,r h-part -> pA
        {
            int gg = bid >> 6, ks = bid & 7, nt = (bid >> 3) & 7;
            rec_mma(h0ch, h0cl, ks * 128,
                    g_wt0h + (size_t)gg * 1024 * 1024, g_wt0l + (size_t)gg * 1024 * 1024,
                    ks * 128, 1024, nt * 128, 4,
                    g_pA + (size_t)ks * 128 * 2048 + gg * 1024, 2048, sm);
        }
        grid_barrier(sense);

        // wait for this step's x-preacts (produced by worker pre tiles)
        if (tid == 0) {
            while (*(volatile unsigned*)&g_pdone[t] < (unsigned)NTPRE) __nanosleep(32);
        }
        __syncthreads();

        // ACT A: rh0 = sig(xr + sum pA[r]) * h0c
        for (int i = bid * 256 + tid; i < BH / 2; i += RECB * 256) {
            size_t idx = (size_t)i * 2;
            int m = (int)(idx >> 10), n = (int)(idx & 1023);
            float2 s = *(const float2*)&xp[(size_t)m * XP3 + 1024 + n];
            #pragma unroll
            for (int p = 0; p < 8; ++p) {
                float2 v = __ldcg((const float2*)&g_pA[((size_t)p * 128 + m) * 2048 + 1024 + n]);
                s.x += v.x; s.y += v.y;
            }
            float2 h = __ldcg((const float2*)&h0c[idx]);
            bsplit2(g_rh0h, g_rh0l, idx, make_float2(sigf(s.x) * h.x, sigf(s.y) * h.y));
        }
        grid_barrier(sense);

        // Phase B: layer0 candidate -> pB
        {
            int ks = bid & 15, nt = bid >> 4;
            rec_mma(g_rh0h, g_rh0l, ks * 64,
                    g_wt0h + (size_t)2 * 1024 * 1024, g_wt0l + (size_t)2 * 1024 * 1024,
                    ks * 64, 1024, nt * 128, 2,
                    g_pB + (size_t)ks * 128 * 1024, 1024, sm);
        }
        grid_barrier(sense);

        // ACT B: h0n = u*h0c + (1-u)*tanh(xc + sum pB)
        for (int i = bid * 256 + tid; i < BH / 2; i += RECB * 256) {
            size_t idx = (size_t)i * 2;
            int m = (int)(idx >> 10), n = (int)(idx & 1023);
            float2 su = *(const float2*)&xp[(size_t)m * XP3 + n];
            #pragma unroll
            for (int p = 0; p < 8; ++p) {
                float2 v = __ldcg((const float2*)&g_pA[((size_t)p * 128 + m) * 2048 + n]);
                su.x += v.x; su.y += v.y;
            }
            float2 sc = *(const float2*)&xp[(size_t)m * XP3 + 2048 + n];
            #pragma unroll
            for (int p = 0; p < 16; ++p) {
                float2 v = __ldcg((const float2*)&g_pB[((size_t)p * 128 + m) * 1024 + n]);
                sc.x += v.x; sc.y += v.y;
            }
            float2 h = __ldcg((const float2*)&h0c[idx]);
            float ux = sigf(su.x), uy = sigf(su.y);
            float2 o = make_float2(ux * h.x + (1.f - ux) * tanhf(sc.x),
                                   uy * h.y + (1.f - uy) * tanhf(sc.y));
            *(float2*)&h0n[idx] = o;
            bsplit2(h0nh, h0nl, idx, o);
        }
        grid_barrier(sense);

        // Phase C: layer1 u,r over [h0n | h1c] -> pC
        {
            int gg = bid >> 6, ks = bid & 7, nt = (bid >> 3) & 7;
            int koff = ks * 256;
            const bf16* ah = (koff < 1024) ? h0nh : h1ch;
            const bf16* al = (koff < 1024) ? h0nl : h1cl;
            rec_mma(ah, al, koff & 1023,
                    g_wt1h + (size_t)gg * 1024 * 2048, g_wt1l + (size_t)gg * 1024 * 2048,
                    koff, 2048, nt * 128, 8,
                    g_pC + (size_t)ks * 128 * 2048 + gg * 1024, 2048, sm);
        }
        grid_barrier(sense);

        // ACT C: rh1 = sig(br1 + sum pC[r]) * h1c
        for (int i = bid * 256 + tid; i < BH / 2; i += RECB * 256) {
            size_t idx = (size_t)i * 2;
            int m = (int)(idx >> 10), n = (int)(idx & 1023);
            float2 s = *(const float2*)&P.br1[n];
            #pragma unroll
            for (int p = 0; p < 8; ++p) {
                float2 v = __ldcg((const float2*)&g_pC[((size_t)p * 128 + m) * 2048 + 1024 + n]);
                s.x += v.x; s.y += v.y;
            }
            float2 h = __ldcg((const float2*)&h1c[idx]);
            bsplit2(g_rh1h, g_rh1l, idx, make_float2(sigf(s.x) * h.x, sigf(s.y) * h.y));
        }
        grid_barrier(sense);

        // Phase D: layer1 candidate over [h0n | rh1] -> pD
        {
            int ks = bid & 15, nt = bid >> 4;
            int koff = ks * 128;
            const bf16* ah = (koff < 1024) ? h0nh : g_rh1h;
            const bf16* al = (koff < 1024) ? h0nl : g_rh1l;
            rec_mma(ah, al, koff & 1023,
                    g_wt1h + (size_t)2 * 1024 * 2048, g_wt1l + (size_t)2 * 1024 * 2048,
                    koff, 2048, nt * 128, 4,
                    g_pD + (size_t)ks * 128 * 1024, 1024, sm);
        }
        grid_barrier(sense);

        // ACT D: h1n; bf16 splits into logits A buffers
        {
            bf16* seqh = g_ah + (size_t)t * BH;
            bf16* seql = g_al + (size_t)t * BH;
            for (int i = bid * 256 + tid; i < BH / 2; i += RECB * 256) {
                size_t idx = (size_t)i * 2;
                int m = (int)(idx >> 10), n = (int)(idx & 1023);
                float2 su = *(const float2*)&P.bu1[n];
                #pragma unroll
                for (int p = 0; p < 8; ++p) {
                    float2 v = __ldcg((const float2*)&g_pC[((size_t)p * 128 + m) * 2048 + n]);
                    su.x += v.x; su.y += v.y;
                }
                float2 sc = *(const float2*)&P.bc1[n];
                #pragma unroll
                for (int p = 0; p < 16; ++p) {
                    float2 v = __ldcg((const float2*)&g_pD[((size_t)p * 128 + m) * 1024 + n]);
                    sc.x += v.x; sc.y += v.y;
                }
                float2 h = __ldcg((const float2*)&h1c[idx]);
                float ux = sigf(su.x), uy = sigf(su.y);
                float2 o = make_float2(ux * h.x + (1.f - ux) * tanhf(sc.x),
                                       uy * h.y + (1.f - uy) * tanhf(sc.y));
                *(float2*)&h1n[idx] = o;
                bsplit2(seqh, seql, idx, o);
                bsplit2(h1nh, h1nl, idx, o);
            }
        }
        grid_barrier(sense);

        // publish step t to logits workers (barrier above ordered the writes)
        if (bid == 0 && tid == 0) {
            __threadfence();
            g_tdone = (unsigned)(t + 1);
        }
    }

    if (bid == 0 && tid == 0) {
        __threadfence();
        g_recdone = 1u;
    }
}

// ---------------- host orchestration ----------------
extern "C" void kernel_launch(void* const* d_in, const int* in_sizes, int n_in,
                              void* d_out, int out_size)
{
    const int*   tok  = (const int*)  d_in[0];
    const float* ihs  = (const float*)d_in[1];
    const float* emb  = (const float*)d_in[2];
    const float* Wout = (const float*)d_in[3];
    const float* bout = (const float*)d_in[4];
    const float* wu0  = (const float*)d_in[5];
    const float* bu0  = (const float*)d_in[6];
    const float* wr0  = (const float*)d_in[7];
    const float* br0  = (const float*)d_in[8];
    const float* wc0  = (const float*)d_in[9];
    const float* bc0  = (const float*)d_in[10];
    const float* wu1  = (const float*)d_in[11];
    const float* bu1  = (const float*)d_in[12];
    const float* wr1  = (const float*)d_in[13];
    const float* br1  = (const float*)d_in[14];
    const float* wc1  = (const float*)d_in[15];
    const float* bc1  = (const float*)d_in[16];

    bf16 *p_ah, *p_al, *p_bth, *p_btl, *p_bxh, *p_bxl;
    bf16 *p_wt0h, *p_wt0l, *p_wt1h, *p_wt1l;
    cudaGetSymbolAddress((void**)&p_ah,  g_ah);
    cudaGetSymbolAddress((void**)&p_al,  g_al);
    cudaGetSymbolAddress((void**)&p_bth, g_bth);
    cudaGetSymbolAddress((void**)&p_btl, g_btl);
    cudaGetSymbolAddress((void**)&p_bxh, g_bxh);
    cudaGetSymbolAddress((void**)&p_bxl, g_bxl);
    cudaGetSymbolAddress((void**)&p_wt0h, g_wt0h);
    cudaGetSymbolAddress((void**)&p_wt0l, g_wt0l);
    cudaGetSymbolAddress((void**)&p_wt1h, g_wt1h);
    cudaGetSymbolAddress((void**)&p_wt1l, g_wt1l);

    const int MM_SMEM = 2 * MM_STG * 2;   // 81920 B
    cudaFuncSetAttribute(mma_gemm_out, cudaFuncAttributeMaxDynamicSharedMemorySize, MM_SMEM);
    cudaFuncSetAttribute(recurrence_kernel, cudaFuncAttributeMaxDynamicSharedMemorySize, MM_SMEM);

    // 1) gather embeddings + bf16 split
    gather_kernel<<<TSEQ * BATCH, 256>>>(tok, emb);

    // 2) ALL weight transposes in one launch
    const size_t EH = (size_t)EMB * HID;
    TJobs TP;
    int base = 0;
    auto setj = [&](int i, const float* W, int ldw, int N, int ldo, bf16* th, bf16* tl,
                    int nbx, int nby) {
        TP.j[i] = {W, ldw, N, ldo, th, tl, nbx, nby, base};
        base += nbx * nby;
    };
    setj(0, wu0,      HID,   HID,   1024, p_bxh,               p_bxl,               32, 32);
    setj(1, wr0,      HID,   HID,   1024, p_bxh + 1024*1024,   p_bxl + 1024*1024,   32, 32);
    setj(2, wc0,      HID,   HID,   1024, p_bxh + 2*1024*1024, p_bxl + 2*1024*1024, 32, 32);
    setj(3, Wout,     VOCAB, VOCAB, 1024, p_bth,               p_btl,               NPAD/32, 32);
    setj(4, wu0 + EH, HID,   HID,   1024, p_wt0h,               p_wt0l,               32, 32);
    setj(5, wr0 + EH, HID,   HID,   1024, p_wt0h + 1024*1024,   p_wt0l + 1024*1024,   32, 32);
    setj(6, wc0 + EH, HID,   HID,   1024, p_wt0h + 2*1024*1024, p_wt0l + 2*1024*1024, 32, 32);
    setj(7, wu1,      HID,   HID,   2048, p_wt1h,               p_wt1l,               32, 64);
    setj(8, wr1,      HID,   HID,   2048, p_wt1h + 1024*2048,   p_wt1l + 1024*2048,   32, 64);
    setj(9, wc1,      HID,   HID,   2048, p_wt1h + 2*1024*2048, p_wt1l + 2*1024*2048, 32, 64);
    TP.total = base;
    dim3 tb(32, 8);
    tconv_all<<<TP.total, tb>>>(TP);

    // 3) initial hidden state + biases + per-launch counter reset
    init_h<<<(BH / 2 + 255) / 256, 256>>>(ihs, bu0, br0, bc0);

    // 4) persistent kernel, 296 CTAs (2/SM): 128 recurrence + 168 workers
    RecParams P{bu1, br1, bc1, bout, (float*)d_out};
    recurrence_kernel<<<GRID, 256, MM_SMEM>>>(P);

    // 5) remaining logits tiles (skips jobs claimed in-recurrence)
    mma_gemm_out<<<dim3(64, NTL), 256, MM_SMEM>>>(p_ah, p_al, p_bth, p_btl,
                                                   bout, (float*)d_out);

    // 6) final states
    state_out<<<(BH + 255) / 256, 256>>>((float*)d_out, (long long)out_size);
}